// round 5
// baseline (speedup 1.0000x reference)
#include <cuda_runtime.h>
#include <cuda_bf16.h>
#include <math.h>
#include <stdint.h>

// Problem constants
#define BB 4
#define NN 2048
#define DD 512
#define HH 8
#define HDIM 64
#define MROWS (BB*NN)          // 8192

// ---------------- scratch (static device globals; no runtime allocation) ---
__device__ float g_qkv[MROWS*1536];
__device__ float g_q[MROWS*DD];
__device__ float g_k[MROWS*DD];
__device__ float g_v[MROWS*DD];
__device__ float g_attn[MROWS*DD];
__device__ float g_hcat[MROWS*1024];
__device__ float g_h1[MROWS*1024];
__device__ float g_xr[MROWS*DD];          // tf32-rounded x
__device__ float g_wr[2621440];           // tf32-rounded weights (all 4)

#define WOFF_QKV  0
#define WOFF_OUT  786432
#define WOFF_FFN1 1048576
#define WOFF_FFN2 2097152

// ------------------------------------------------------------ tf32 utils ---
__device__ __forceinline__ uint32_t f2tf32(float x) {
    uint32_t u;
    asm volatile("cvt.rna.tf32.f32 %0, %1;" : "=r"(u) : "f"(x));
    return u;
}
__device__ __forceinline__ float roundtf(float x) {
    return __uint_as_float(f2tf32(x));
}

__device__ __forceinline__ void mma_tf32(float c[4],
                                         const uint32_t a[4],
                                         const uint32_t b[2]) {
    asm volatile(
        "mma.sync.aligned.m16n8k8.row.col.f32.tf32.tf32.f32 "
        "{%0,%1,%2,%3}, {%4,%5,%6,%7}, {%8,%9}, {%0,%1,%2,%3};\n"
        : "+f"(c[0]), "+f"(c[1]), "+f"(c[2]), "+f"(c[3])
        : "r"(a[0]), "r"(a[1]), "r"(a[2]), "r"(a[3]),
          "r"(b[0]), "r"(b[1]));
}

__device__ __forceinline__ void cp_async16(uint32_t saddr, const void* gptr) {
    asm volatile("cp.async.cg.shared.global [%0], [%1], 16;\n"
                 :: "r"(saddr), "l"(gptr));
}
#define CP_COMMIT() asm volatile("cp.async.commit_group;\n" ::: "memory")
#define CP_WAIT1()  asm volatile("cp.async.wait_group 1;\n" ::: "memory")
#define CP_WAIT0()  asm volatile("cp.async.wait_group 0;\n" ::: "memory")

// --------------------------- pre-round x + weights, and fill hcat left half
__global__ __launch_bounds__(256) void round_inputs(
    const float* __restrict__ x,
    const float* __restrict__ w_qkv,
    const float* __restrict__ w_out,
    const float* __restrict__ w_ffn1,
    const float* __restrict__ w_ffn2)
{
    int idx = blockIdx.x * blockDim.x + threadIdx.x;  // float4 index
    const int nx = MROWS*DD/4;
    const int n0 = 786432/4;
    const int n1 = 262144/4;
    const int n2 = 1048576/4;
    const int n3 = 524288/4;
    if (idx < nx) {
        float4 v = ((const float4*)x)[idx];
        v.x = roundtf(v.x); v.y = roundtf(v.y);
        v.z = roundtf(v.z); v.w = roundtf(v.w);
        ((float4*)g_xr)[idx] = v;
        int m = idx >> 7, j = idx & 127;
        ((float4*)g_hcat)[m * 256 + j] = v;   // hcat[:, 0:512] = round(x)
        return;
    }
    int t = idx - nx;
    const float4* src; float4* dst;
    if (t < n0)                 { src = (const float4*)w_qkv + t;  dst = (float4*)(g_wr + WOFF_QKV) + t; }
    else if ((t -= n0) < n1)    { src = (const float4*)w_out + t;  dst = (float4*)(g_wr + WOFF_OUT) + t; }
    else if ((t -= n1) < n2)    { src = (const float4*)w_ffn1 + t; dst = (float4*)(g_wr + WOFF_FFN1) + t; }
    else if ((t -= n2) < n3)    { src = (const float4*)w_ffn2 + t; dst = (float4*)(g_wr + WOFF_FFN2) + t; }
    else return;
    float4 v = *src;
    v.x = roundtf(v.x); v.y = roundtf(v.y);
    v.z = roundtf(v.z); v.w = roundtf(v.w);
    *dst = v;
}

// --------------------------------------------- pipelined tf32 GEMM ---------
#define GBM 128
#define GBN 128
#define GBK 16
#define APADW 20
#define BPADW 136

__global__ __launch_bounds__(256) void gemm_tf32(
    const float* __restrict__ A, int lda,
    const float* __restrict__ Bm, int ldb,
    float* __restrict__ C, int ldc,
    const float* __restrict__ bias,
    const float* __restrict__ res, int ldres,
    int K, int roundC)
{
    __shared__ uint32_t As[2][GBM * APADW];
    __shared__ uint32_t Bs[2][GBK * BPADW];

    const int tid  = threadIdx.x;
    const int brow = blockIdx.y * GBM;
    const int bcol = blockIdx.x * GBN;
    const int w    = tid >> 5;
    const int lane = tid & 31;
    const int g    = lane >> 2;
    const int tg   = lane & 3;
    const int wm   = (w & 1) * 64;
    const int wn   = (w >> 1) * 32;

    const int ar0 = tid >> 2,  ac0 = (tid & 3) * 4;
    const int ar1 = ar0 + 64;
    const int bk0 = tid >> 5,  bn0 = (tid & 31) * 4;
    const int bk1 = bk0 + 8;

    uint32_t sA0[2], sA1[2], sB0[2], sB1[2];
    #pragma unroll
    for (int s = 0; s < 2; s++) {
        sA0[s] = (uint32_t)__cvta_generic_to_shared(&As[s][ar0 * APADW + ac0]);
        sA1[s] = (uint32_t)__cvta_generic_to_shared(&As[s][ar1 * APADW + ac0]);
        sB0[s] = (uint32_t)__cvta_generic_to_shared(&Bs[s][bk0 * BPADW + bn0]);
        sB1[s] = (uint32_t)__cvta_generic_to_shared(&Bs[s][bk1 * BPADW + bn0]);
    }

    float acc[4][4][4];
    #pragma unroll
    for (int mi = 0; mi < 4; mi++)
        #pragma unroll
        for (int ni = 0; ni < 4; ni++)
            #pragma unroll
            for (int q = 0; q < 4; q++) acc[mi][ni][q] = 0.f;

    const int nk = K / GBK;

    {
        cp_async16(sA0[0], &A[(size_t)(brow + ar0) * lda + ac0]);
        cp_async16(sA1[0], &A[(size_t)(brow + ar1) * lda + ac0]);
        cp_async16(sB0[0], &Bm[(size_t)(bk0) * ldb + bcol + bn0]);
        cp_async16(sB1[0], &Bm[(size_t)(bk1) * ldb + bcol + bn0]);
        CP_COMMIT();
    }

    for (int kt = 0; kt < nk; kt++) {
        const int s = kt & 1;
        if (kt + 1 < nk) {
            const int k0 = (kt + 1) * GBK;
            cp_async16(sA0[s^1], &A[(size_t)(brow + ar0) * lda + k0 + ac0]);
            cp_async16(sA1[s^1], &A[(size_t)(brow + ar1) * lda + k0 + ac0]);
            cp_async16(sB0[s^1], &Bm[(size_t)(k0 + bk0) * ldb + bcol + bn0]);
            cp_async16(sB1[s^1], &Bm[(size_t)(k0 + bk1) * ldb + bcol + bn0]);
            CP_COMMIT();
            CP_WAIT1();
        } else {
            CP_WAIT0();
        }
        __syncthreads();

        #pragma unroll
        for (int ks = 0; ks < 2; ks++) {
            const int kk = ks * 8;
            uint32_t af[4][4], bf[4][2];
            #pragma unroll
            for (int mi = 0; mi < 4; mi++) {
                int r = wm + mi * 16 + g;
                af[mi][0] = As[s][r * APADW + kk + tg];
                af[mi][1] = As[s][(r + 8) * APADW + kk + tg];
                af[mi][2] = As[s][r * APADW + kk + tg + 4];
                af[mi][3] = As[s][(r + 8) * APADW + kk + tg + 4];
            }
            #pragma unroll
            for (int ni = 0; ni < 4; ni++) {
                int cc = wn + ni * 8 + g;
                bf[ni][0] = Bs[s][(kk + tg) * BPADW + cc];
                bf[ni][1] = Bs[s][(kk + tg + 4) * BPADW + cc];
            }
            #pragma unroll
            for (int mi = 0; mi < 4; mi++)
                #pragma unroll
                for (int ni = 0; ni < 4; ni++)
                    mma_tf32(acc[mi][ni], af[mi], bf[ni]);
        }
        __syncthreads();
    }

    #pragma unroll
    for (int mi = 0; mi < 4; mi++) {
        int r0 = brow + wm + mi * 16 + g;
        int r1 = r0 + 8;
        #pragma unroll
        for (int ni = 0; ni < 4; ni++) {
            int cc = bcol + wn + ni * 8 + tg * 2;
            float2 b2 = *(const float2*)&bias[cc];
            float v0 = acc[mi][ni][0] + b2.x;
            float v1 = acc[mi][ni][1] + b2.y;
            float v2 = acc[mi][ni][2] + b2.x;
            float v3 = acc[mi][ni][3] + b2.y;
            if (res) {
                float2 ra = *(const float2*)&res[(size_t)r0 * ldres + cc];
                float2 rb = *(const float2*)&res[(size_t)r1 * ldres + cc];
                v0 += ra.x; v1 += ra.y; v2 += rb.x; v3 += rb.y;
            }
            if (roundC) {
                v0 = roundtf(v0); v1 = roundtf(v1);
                v2 = roundtf(v2); v3 = roundtf(v3);
            }
            *(float2*)&C[(size_t)r0 * ldc + cc] = make_float2(v0, v1);
            *(float2*)&C[(size_t)r1 * ldc + cc] = make_float2(v2, v3);
        }
    }
}

// ------------------------------------------------------------ RoPE split ---
__global__ void rope_kernel(const float* __restrict__ freqs)
{
    int idx = blockIdx.x * blockDim.x + threadIdx.x;
    if (idx >= BB * NN * HH * 32) return;
    int i = idx & 31;
    int h = (idx >> 5) & 7;
    int n = (idx >> 8) & 2047;
    int b = idx >> 19;

    float f = freqs[(b * NN + n) * 32 + i];
    float c = cosf(f), s = sinf(f);

    int base = (b * NN + n) * 1536 + h * 64;
    int ob   = ((b * HH + h) * NN + n) * 64 + 2 * i;

    float q1 = g_qkv[base + 2*i], q2 = g_qkv[base + 2*i + 1];
    g_q[ob]     = roundtf(q1 * c - q2 * s);
    g_q[ob + 1] = roundtf(q1 * s + q2 * c);

    float k1 = g_qkv[base + 512 + 2*i], k2 = g_qkv[base + 512 + 2*i + 1];
    g_k[ob]     = roundtf(k1 * c - k2 * s);
    g_k[ob + 1] = roundtf(k1 * s + k2 * c);

    g_v[ob]     = roundtf(g_qkv[base + 1024 + 2*i]);
    g_v[ob + 1] = roundtf(g_qkv[base + 1024 + 2*i + 1]);
}

// ---------------------------------------------- tensor-core flash attention
// 128 queries per CTA, 4 warps x 32 q-rows (2 m-tiles). Q frags in registers.
// K/V smem columns permuted: pi(k) = (k&~7)|((k&3)<<1)|((k>>2)&1) so that
// B-fragment pairs (tg, tg+4) are adjacent -> single LDS.64.
#define AST 68
#define ATT_SMEM ((64 + 64 + 128) * AST * 4)   // Ks + Vst + Ps = 69632

__global__ __launch_bounds__(128, 2) void attn_tc()
{
    const int bh = blockIdx.y;
    const int q0 = blockIdx.x * 128;
    const float* __restrict__ Qg = g_q + (size_t)bh * NN * HDIM;
    const float* __restrict__ Kg = g_k + (size_t)bh * NN * HDIM;
    const float* __restrict__ Vg = g_v + (size_t)bh * NN * HDIM;

    extern __shared__ uint32_t smu[];
    uint32_t* Ks  = smu;                  // [key][pi(d)]
    uint32_t* Vst = smu + 64 * AST;       // [d][pi(key)]
    uint32_t* Ps  = smu + 128 * AST;      // [q][k]

    const int tid  = threadIdx.x;
    const int w    = tid >> 5;
    const int lane = tid & 31;
    const int g    = lane >> 2;
    const int tg   = lane & 3;
    const int w32  = w * 32;

    // ---- Q fragments to registers (tile-invariant) ----
    uint32_t qa[2][8][4];
    #pragma unroll
    for (int mt = 0; mt < 2; mt++) {
        const int r = q0 + w32 + mt * 16 + g;
        #pragma unroll
        for (int ks = 0; ks < 8; ks++) {
            const int d = ks * 8 + tg;
            qa[mt][ks][0] = __float_as_uint(Qg[(size_t)r * 64 + d] * 0.125f);
            qa[mt][ks][1] = __float_as_uint(Qg[(size_t)(r + 8) * 64 + d] * 0.125f);
            qa[mt][ks][2] = __float_as_uint(Qg[(size_t)r * 64 + d + 4] * 0.125f);
            qa[mt][ks][3] = __float_as_uint(Qg[(size_t)(r + 8) * 64 + d + 4] * 0.125f);
        }
    }

    float mm[2][2], ll[2][2];
    #pragma unroll
    for (int mt = 0; mt < 2; mt++) {
        mm[mt][0] = -1e30f; mm[mt][1] = -1e30f;
        ll[mt][0] = 0.f;    ll[mt][1] = 0.f;
    }
    float oacc[2][8][4];
    #pragma unroll
    for (int mt = 0; mt < 2; mt++)
        #pragma unroll
        for (int nt = 0; nt < 8; nt++)
            #pragma unroll
            for (int q = 0; q < 4; q++) oacc[mt][nt][q] = 0.f;

    // load mappings
    const int kr   = tid >> 1;                 // 0..63 key row
    const int kdb  = (tid & 1) * 32;           // d base 0/32
    const int kpb0 = kdb | ((kdb >> 2) & 1);   // pi base contribution (d%8==0 -> (d>>2)&1 per 4-chunk)
    const int vk   = tid & 63;                 // key
    const int vpk  = (vk & ~7) | ((vk & 3) << 1) | ((vk >> 2) & 1);
    const int vdb  = (tid >> 6) * 32;          // d base 0/32

    for (int k0 = 0; k0 < NN; k0 += 64) {
        __syncthreads();   // prev tile's S (Ks) and PV (Vst) reads done
        // ---- K tile: store with pi(d) column permutation ----
        #pragma unroll
        for (int c = 0; c < 8; c++) {
            const int d = kdb + c * 4;                       // d%4==0
            float4 v = *(const float4*)&Kg[(size_t)(k0 + kr) * 64 + d];
            const int pb = (d & ~7) | ((d >> 2) & 1);
            uint32_t* row = &Ks[kr * AST];
            row[pb + 0] = __float_as_uint(v.x);
            row[pb + 2] = __float_as_uint(v.y);
            row[pb + 4] = __float_as_uint(v.z);
            row[pb + 6] = __float_as_uint(v.w);
        }
        // ---- V tile: transpose, pi(key) column permutation ----
        #pragma unroll
        for (int c = 0; c < 8; c++) {
            const int d = vdb + c * 4;
            float4 v = *(const float4*)&Vg[(size_t)(k0 + vk) * 64 + d];
            Vst[(d + 0) * AST + vpk] = __float_as_uint(v.x);
            Vst[(d + 1) * AST + vpk] = __float_as_uint(v.y);
            Vst[(d + 2) * AST + vpk] = __float_as_uint(v.z);
            Vst[(d + 3) * AST + vpk] = __float_as_uint(v.w);
        }
        __syncthreads();

        // ---- S = Q K^T ----
        float sacc[2][8][4];
        #pragma unroll
        for (int mt = 0; mt < 2; mt++)
            #pragma unroll
            for (int nt = 0; nt < 8; nt++)
                #pragma unroll
                for (int q = 0; q < 4; q++) sacc[mt][nt][q] = 0.f;

        #pragma unroll
        for (int ks = 0; ks < 8; ks++) {
            const int kk = ks * 8 + tg * 2;
            #pragma unroll
            for (int nt = 0; nt < 8; nt++) {
                uint2 bv = *(const uint2*)&Ks[(nt * 8 + g) * AST + kk];
                uint32_t b[2] = {bv.x, bv.y};
                mma_tf32(sacc[0][nt], qa[0][ks], b);
                mma_tf32(sacc[1][nt], qa[1][ks], b);
            }
        }

        // ---- online softmax per m-tile ----
        #pragma unroll
        for (int mt = 0; mt < 2; mt++) {
            float mt0 = -1e30f, mt1 = -1e30f;
            #pragma unroll
            for (int nt = 0; nt < 8; nt++) {
                mt0 = fmaxf(mt0, fmaxf(sacc[mt][nt][0], sacc[mt][nt][1]));
                mt1 = fmaxf(mt1, fmaxf(sacc[mt][nt][2], sacc[mt][nt][3]));
            }
            mt0 = fmaxf(mt0, __shfl_xor_sync(0xffffffffu, mt0, 1));
            mt0 = fmaxf(mt0, __shfl_xor_sync(0xffffffffu, mt0, 2));
            mt1 = fmaxf(mt1, __shfl_xor_sync(0xffffffffu, mt1, 1));
            mt1 = fmaxf(mt1, __shfl_xor_sync(0xffffffffu, mt1, 2));
            float mn0 = fmaxf(mm[mt][0], mt0), mn1 = fmaxf(mm[mt][1], mt1);

            float rs0 = 0.f, rs1 = 0.f;
            #pragma unroll
            for (int nt = 0; nt < 8; nt++) {
                sacc[mt][nt][0] = __expf(sacc[mt][nt][0] - mn0);
                sacc[mt][nt][1] = __expf(sacc[mt][nt][1] - mn0);
                sacc[mt][nt][2] = __expf(sacc[mt][nt][2] - mn1);
                sacc[mt][nt][3] = __expf(sacc[mt][nt][3] - mn1);
                rs0 += sacc[mt][nt][0] + sacc[mt][nt][1];
                rs1 += sacc[mt][nt][2] + sacc[mt][nt][3];
            }
            rs0 += __shfl_xor_sync(0xffffffffu, rs0, 1);
            rs0 += __shfl_xor_sync(0xffffffffu, rs0, 2);
            rs1 += __shfl_xor_sync(0xffffffffu, rs1, 1);
            rs1 += __shfl_xor_sync(0xffffffffu, rs1, 2);

            float c0 = __expf(mm[mt][0] - mn0), c1 = __expf(mm[mt][1] - mn1);
            ll[mt][0] = ll[mt][0] * c0 + rs0;
            ll[mt][1] = ll[mt][1] * c1 + rs1;
            mm[mt][0] = mn0; mm[mt][1] = mn1;
            #pragma unroll
            for (int nt = 0; nt < 8; nt++) {
                oacc[mt][nt][0] *= c0; oacc[mt][nt][1] *= c0;
                oacc[mt][nt][2] *= c1; oacc[mt][nt][3] *= c1;
            }

            // P -> smem (warp-private rows)
            const int pr = w32 + mt * 16 + g;
            #pragma unroll
            for (int nt = 0; nt < 8; nt++) {
                uint2 u0, u1;
                u0.x = f2tf32(sacc[mt][nt][0]); u0.y = f2tf32(sacc[mt][nt][1]);
                u1.x = f2tf32(sacc[mt][nt][2]); u1.y = f2tf32(sacc[mt][nt][3]);
                *(uint2*)&Ps[pr * AST + nt * 8 + tg * 2]       = u0;
                *(uint2*)&Ps[(pr + 8) * AST + nt * 8 + tg * 2] = u1;
            }
        }
        __syncwarp();

        // ---- O += P @ V ----
        #pragma unroll
        for (int ks = 0; ks < 8; ks++) {
            const int kk = ks * 8;
            uint32_t a0[4], a1[4];
            a0[0] = Ps[(w32 + g) * AST + kk + tg];
            a0[1] = Ps[(w32 + g + 8) * AST + kk + tg];
            a0[2] = Ps[(w32 + g) * AST + kk + tg + 4];
            a0[3] = Ps[(w32 + g + 8) * AST + kk + tg + 4];
            a1[0] = Ps[(w32 + 16 + g) * AST + kk + tg];
            a1[1] = Ps[(w32 + 16 + g + 8) * AST + kk + tg];
            a1[2] = Ps[(w32 + 16 + g) * AST + kk + tg + 4];
            a1[3] = Ps[(w32 + 16 + g + 8) * AST + kk + tg + 4];
            const int kc = kk + tg * 2;
            #pragma unroll
            for (int nt = 0; nt < 8; nt++) {
                uint2 bv = *(const uint2*)&Vst[(nt * 8 + g) * AST + kc];
                uint32_t b[2] = {bv.x, bv.y};
                mma_tf32(oacc[0][nt], a0, b);
                mma_tf32(oacc[1][nt], a1, b);
            }
        }
    }

    // ---- write out [B,N,D], tf32-rounded ----
    const int b = bh >> 3, h = bh & 7;
    #pragma unroll
    for (int mt = 0; mt < 2; mt++) {
        const float inv0 = 1.f / ll[mt][0], inv1 = 1.f / ll[mt][1];
        const int r0 = q0 + w32 + mt * 16 + g, r1 = r0 + 8;
        #pragma unroll
        for (int nt = 0; nt < 8; nt++) {
            int d = h * 64 + nt * 8 + tg * 2;
            *(float2*)&g_attn[(size_t)(b * NN + r0) * DD + d] =
                make_float2(roundtf(oacc[mt][nt][0] * inv0), roundtf(oacc[mt][nt][1] * inv0));
            *(float2*)&g_attn[(size_t)(b * NN + r1) * DD + d] =
                make_float2(roundtf(oacc[mt][nt][2] * inv1), roundtf(oacc[mt][nt][3] * inv1));
        }
    }
}

// ------------------------------------------------------- LayerNorm + GELU --
__global__ __launch_bounds__(256) void ln_gelu_kernel(
    const float* __restrict__ gamma, const float* __restrict__ beta)
{
    const int r = blockIdx.x;
    const int t = threadIdx.x;
    float4 v = *(const float4*)&g_h1[(size_t)r * 1024 + t * 4];

    float sum = v.x + v.y + v.z + v.w;
    float sq  = v.x*v.x + v.y*v.y + v.z*v.z + v.w*v.w;
    #pragma unroll
    for (int off = 16; off >= 1; off >>= 1) {
        sum += __shfl_xor_sync(0xffffffffu, sum, off);
        sq  += __shfl_xor_sync(0xffffffffu, sq, off);
    }
    __shared__ float ssum[8], ssq[8];
    if ((t & 31) == 0) { ssum[t >> 5] = sum; ssq[t >> 5] = sq; }
    __syncthreads();
    float tot = 0.f, totq = 0.f;
    #pragma unroll
    for (int w = 0; w < 8; w++) { tot += ssum[w]; totq += ssq[w]; }

    float mean = tot * (1.f / 1024.f);
    float var  = totq * (1.f / 1024.f) - mean * mean;
    float inv  = rsqrtf(var + 1e-5f);

    float4 g4 = *(const float4*)&gamma[t * 4];
    float4 b4 = *(const float4*)&beta[t * 4];
    float y; float4 o;
    y = (v.x - mean) * inv * g4.x + b4.x; o.x = roundtf(0.5f * y * (1.f + erff(y * 0.70710678f)));
    y = (v.y - mean) * inv * g4.y + b4.y; o.y = roundtf(0.5f * y * (1.f + erff(y * 0.70710678f)));
    y = (v.z - mean) * inv * g4.z + b4.z; o.z = roundtf(0.5f * y * (1.f + erff(y * 0.70710678f)));
    y = (v.w - mean) * inv * g4.w + b4.w; o.w = roundtf(0.5f * y * (1.f + erff(y * 0.70710678f)));
    *(float4*)&g_h1[(size_t)r * 1024 + t * 4] = o;
}

// ------------------------------------------------------------- launcher ----
extern "C" void kernel_launch(void* const* d_in, const int* in_sizes, int n_in,
                              void* d_out, int out_size)
{
    const float* x      = (const float*)d_in[0];
    const float* freqs  = (const float*)d_in[1];
    const float* wqkv_w = (const float*)d_in[2];
    const float* wqkv_b = (const float*)d_in[3];
    const float* out_w  = (const float*)d_in[4];
    const float* out_b  = (const float*)d_in[5];
    const float* ffn1_w = (const float*)d_in[6];
    const float* ffn1_b = (const float*)d_in[7];
    const float* ln_g   = (const float*)d_in[8];
    const float* ln_b   = (const float*)d_in[9];
    const float* ffn2_w = (const float*)d_in[10];
    const float* ffn2_b = (const float*)d_in[11];
    float* out = (float*)d_out;

    float *p_qkv, *p_attn, *p_hcat, *p_h1, *p_xr, *p_wr;
    cudaGetSymbolAddress((void**)&p_qkv,  g_qkv);
    cudaGetSymbolAddress((void**)&p_attn, g_attn);
    cudaGetSymbolAddress((void**)&p_hcat, g_hcat);
    cudaGetSymbolAddress((void**)&p_h1,   g_h1);
    cudaGetSymbolAddress((void**)&p_xr,   g_xr);
    cudaGetSymbolAddress((void**)&p_wr,   g_wr);

    cudaFuncSetAttribute(attn_tc,
                         cudaFuncAttributeMaxDynamicSharedMemorySize, ATT_SMEM);

    // 0. round x + all weights to tf32; also fill hcat[:,0:512]
    {
        int total_f4 = MROWS*DD/4 + (786432 + 262144 + 1048576 + 524288)/4;
        round_inputs<<<(total_f4 + 255)/256, 256>>>(x, wqkv_w, out_w, ffn1_w, ffn2_w);
    }

    // 1. QKV projection: [8192,512] @ [512,1536]
    gemm_tf32<<<dim3(1536/GBN, MROWS/GBM), 256>>>(
        p_xr, DD, p_wr + WOFF_QKV, 1536, p_qkv, 1536, wqkv_b, nullptr, 0, DD, 0);

    // 2. RoPE + head split (stores rounded)
    rope_kernel<<<(BB*NN*HH*32 + 255)/256, 256>>>(freqs);

    // 3. Attention (tf32 tensor cores, 4-warp CTA, m=32/warp)
    attn_tc<<<dim3(NN/128, BB*HH), 128, ATT_SMEM>>>();

    // 4. out-proj into hcat right half (rounded): [8192,512]@[512,512]
    gemm_tf32<<<dim3(512/GBN, MROWS/GBM), 256>>>(
        p_attn, DD, p_wr + WOFF_OUT, DD, p_hcat + 512, 1024, out_b, nullptr, 0, DD, 1);

    // 5. FFN1: [8192,1024]@[1024,1024]
    gemm_tf32<<<dim3(1024/GBN, MROWS/GBM), 256>>>(
        p_hcat, 1024, p_wr + WOFF_FFN1, 1024, p_h1, 1024, ffn1_b, nullptr, 0, 1024, 0);

    // 6. LayerNorm + exact GELU (in place, stores rounded)
    ln_gelu_kernel<<<MROWS, 256>>>(ln_g, ln_b);

    // 7. FFN2 + residual: out = x + h1 @ [1024,512] + b
    gemm_tf32<<<dim3(512/GBN, MROWS/GBM), 256>>>(
        p_h1, 1024, p_wr + WOFF_FFN2, DD, out, DD, ffn2_b, x, DD, 1024, 0);
}

// round 7
// speedup vs baseline: 1.2793x; 1.2793x over previous
#include <cuda_runtime.h>
#include <cuda_bf16.h>
#include <math.h>
#include <stdint.h>

// Problem constants
#define BB 4
#define NN 2048
#define DD 512
#define HH 8
#define HDIM 64
#define MROWS (BB*NN)          // 8192

// ---------------- scratch (static device globals; no runtime allocation) ---
__device__ float g_qkv[MROWS*1536];
__device__ float g_q[MROWS*DD];
__device__ float g_k[MROWS*DD];
__device__ float g_v[MROWS*DD];
__device__ float g_attn[MROWS*DD];
__device__ float g_hcat[MROWS*1024];
__device__ float g_h1[MROWS*1024];
__device__ float g_xr[MROWS*DD];          // tf32-rounded x
__device__ float g_wr[2621440];           // tf32-rounded weights (all 4)

#define WOFF_QKV  0
#define WOFF_OUT  786432
#define WOFF_FFN1 1048576
#define WOFF_FFN2 2097152

// ------------------------------------------------------------ tf32 utils ---
__device__ __forceinline__ uint32_t f2tf32(float x) {
    uint32_t u;
    asm volatile("cvt.rna.tf32.f32 %0, %1;" : "=r"(u) : "f"(x));
    return u;
}
__device__ __forceinline__ float roundtf(float x) {
    return __uint_as_float(f2tf32(x));
}
// pack two f32 -> bf16x2 (lo = a, hi = b)
__device__ __forceinline__ uint32_t pack_bf16(float a, float b) {
    uint32_t r;
    asm("cvt.rn.bf16x2.f32 %0, %1, %2;" : "=r"(r) : "f"(b), "f"(a));
    return r;
}

__device__ __forceinline__ void mma_tf32(float c[4],
                                         const uint32_t a[4],
                                         const uint32_t b[2]) {
    asm volatile(
        "mma.sync.aligned.m16n8k8.row.col.f32.tf32.tf32.f32 "
        "{%0,%1,%2,%3}, {%4,%5,%6,%7}, {%8,%9}, {%0,%1,%2,%3};\n"
        : "+f"(c[0]), "+f"(c[1]), "+f"(c[2]), "+f"(c[3])
        : "r"(a[0]), "r"(a[1]), "r"(a[2]), "r"(a[3]),
          "r"(b[0]), "r"(b[1]));
}

__device__ __forceinline__ void mma_bf16(float c[4],
                                         const uint32_t a[4],
                                         uint32_t b0, uint32_t b1) {
    asm volatile(
        "mma.sync.aligned.m16n8k16.row.col.f32.bf16.bf16.f32 "
        "{%0,%1,%2,%3}, {%4,%5,%6,%7}, {%8,%9}, {%0,%1,%2,%3};\n"
        : "+f"(c[0]), "+f"(c[1]), "+f"(c[2]), "+f"(c[3])
        : "r"(a[0]), "r"(a[1]), "r"(a[2]), "r"(a[3]),
          "r"(b0), "r"(b1));
}

__device__ __forceinline__ void cp_async16(uint32_t saddr, const void* gptr) {
    asm volatile("cp.async.cg.shared.global [%0], [%1], 16;\n"
                 :: "r"(saddr), "l"(gptr));
}
#define CP_COMMIT() asm volatile("cp.async.commit_group;\n" ::: "memory")
#define CP_WAIT1()  asm volatile("cp.async.wait_group 1;\n" ::: "memory")
#define CP_WAIT0()  asm volatile("cp.async.wait_group 0;\n" ::: "memory")

// --------------------------- pre-round x + weights, and fill hcat left half
__global__ __launch_bounds__(256) void round_inputs(
    const float* __restrict__ x,
    const float* __restrict__ w_qkv,
    const float* __restrict__ w_out,
    const float* __restrict__ w_ffn1,
    const float* __restrict__ w_ffn2)
{
    int idx = blockIdx.x * blockDim.x + threadIdx.x;  // float4 index
    const int nx = MROWS*DD/4;
    const int n0 = 786432/4;
    const int n1 = 262144/4;
    const int n2 = 1048576/4;
    const int n3 = 524288/4;
    if (idx < nx) {
        float4 v = ((const float4*)x)[idx];
        v.x = roundtf(v.x); v.y = roundtf(v.y);
        v.z = roundtf(v.z); v.w = roundtf(v.w);
        ((float4*)g_xr)[idx] = v;
        int m = idx >> 7, j = idx & 127;
        ((float4*)g_hcat)[m * 256 + j] = v;   // hcat[:, 0:512] = round(x)
        return;
    }
    int t = idx - nx;
    const float4* src; float4* dst;
    if (t < n0)                 { src = (const float4*)w_qkv + t;  dst = (float4*)(g_wr + WOFF_QKV) + t; }
    else if ((t -= n0) < n1)    { src = (const float4*)w_out + t;  dst = (float4*)(g_wr + WOFF_OUT) + t; }
    else if ((t -= n1) < n2)    { src = (const float4*)w_ffn1 + t; dst = (float4*)(g_wr + WOFF_FFN1) + t; }
    else if ((t -= n2) < n3)    { src = (const float4*)w_ffn2 + t; dst = (float4*)(g_wr + WOFF_FFN2) + t; }
    else return;
    float4 v = *src;
    v.x = roundtf(v.x); v.y = roundtf(v.y);
    v.z = roundtf(v.z); v.w = roundtf(v.w);
    *dst = v;
}

// --------------------------------------------- pipelined tf32 GEMM (R4) ----
#define GBM 128
#define GBN 128
#define GBK 16
#define APADW 20
#define BPADW 136

__global__ __launch_bounds__(256) void gemm_tf32(
    const float* __restrict__ A, int lda,
    const float* __restrict__ Bm, int ldb,
    float* __restrict__ C, int ldc,
    const float* __restrict__ bias,
    const float* __restrict__ res, int ldres,
    int K, int roundC)
{
    __shared__ uint32_t As[2][GBM * APADW];
    __shared__ uint32_t Bs[2][GBK * BPADW];

    const int tid  = threadIdx.x;
    const int brow = blockIdx.y * GBM;
    const int bcol = blockIdx.x * GBN;
    const int w    = tid >> 5;
    const int lane = tid & 31;
    const int g    = lane >> 2;
    const int tg   = lane & 3;
    const int wm   = (w & 1) * 64;
    const int wn   = (w >> 1) * 32;

    const int ar0 = tid >> 2,  ac0 = (tid & 3) * 4;
    const int ar1 = ar0 + 64;
    const int bk0 = tid >> 5,  bn0 = (tid & 31) * 4;
    const int bk1 = bk0 + 8;

    uint32_t sA0[2], sA1[2], sB0[2], sB1[2];
    #pragma unroll
    for (int s = 0; s < 2; s++) {
        sA0[s] = (uint32_t)__cvta_generic_to_shared(&As[s][ar0 * APADW + ac0]);
        sA1[s] = (uint32_t)__cvta_generic_to_shared(&As[s][ar1 * APADW + ac0]);
        sB0[s] = (uint32_t)__cvta_generic_to_shared(&Bs[s][bk0 * BPADW + bn0]);
        sB1[s] = (uint32_t)__cvta_generic_to_shared(&Bs[s][bk1 * BPADW + bn0]);
    }

    float acc[4][4][4];
    #pragma unroll
    for (int mi = 0; mi < 4; mi++)
        #pragma unroll
        for (int ni = 0; ni < 4; ni++)
            #pragma unroll
            for (int q = 0; q < 4; q++) acc[mi][ni][q] = 0.f;

    const int nk = K / GBK;

    {
        cp_async16(sA0[0], &A[(size_t)(brow + ar0) * lda + ac0]);
        cp_async16(sA1[0], &A[(size_t)(brow + ar1) * lda + ac0]);
        cp_async16(sB0[0], &Bm[(size_t)(bk0) * ldb + bcol + bn0]);
        cp_async16(sB1[0], &Bm[(size_t)(bk1) * ldb + bcol + bn0]);
        CP_COMMIT();
    }

    for (int kt = 0; kt < nk; kt++) {
        const int s = kt & 1;
        if (kt + 1 < nk) {
            const int k0 = (kt + 1) * GBK;
            cp_async16(sA0[s^1], &A[(size_t)(brow + ar0) * lda + k0 + ac0]);
            cp_async16(sA1[s^1], &A[(size_t)(brow + ar1) * lda + k0 + ac0]);
            cp_async16(sB0[s^1], &Bm[(size_t)(k0 + bk0) * ldb + bcol + bn0]);
            cp_async16(sB1[s^1], &Bm[(size_t)(k0 + bk1) * ldb + bcol + bn0]);
            CP_COMMIT();
            CP_WAIT1();
        } else {
            CP_WAIT0();
        }
        __syncthreads();

        #pragma unroll
        for (int ks = 0; ks < 2; ks++) {
            const int kk = ks * 8;
            uint32_t af[4][4], bf[4][2];
            #pragma unroll
            for (int mi = 0; mi < 4; mi++) {
                int r = wm + mi * 16 + g;
                af[mi][0] = As[s][r * APADW + kk + tg];
                af[mi][1] = As[s][(r + 8) * APADW + kk + tg];
                af[mi][2] = As[s][r * APADW + kk + tg + 4];
                af[mi][3] = As[s][(r + 8) * APADW + kk + tg + 4];
            }
            #pragma unroll
            for (int ni = 0; ni < 4; ni++) {
                int cc = wn + ni * 8 + g;
                bf[ni][0] = Bs[s][(kk + tg) * BPADW + cc];
                bf[ni][1] = Bs[s][(kk + tg + 4) * BPADW + cc];
            }
            #pragma unroll
            for (int mi = 0; mi < 4; mi++)
                #pragma unroll
                for (int ni = 0; ni < 4; ni++)
                    mma_tf32(acc[mi][ni], af[mi], bf[ni]);
        }
        __syncthreads();
    }

    #pragma unroll
    for (int mi = 0; mi < 4; mi++) {
        int r0 = brow + wm + mi * 16 + g;
        int r1 = r0 + 8;
        #pragma unroll
        for (int ni = 0; ni < 4; ni++) {
            int cc = bcol + wn + ni * 8 + tg * 2;
            float2 b2 = *(const float2*)&bias[cc];
            float v0 = acc[mi][ni][0] + b2.x;
            float v1 = acc[mi][ni][1] + b2.y;
            float v2 = acc[mi][ni][2] + b2.x;
            float v3 = acc[mi][ni][3] + b2.y;
            if (res) {
                float2 ra = *(const float2*)&res[(size_t)r0 * ldres + cc];
                float2 rb = *(const float2*)&res[(size_t)r1 * ldres + cc];
                v0 += ra.x; v1 += ra.y; v2 += rb.x; v3 += rb.y;
            }
            if (roundC) {
                v0 = roundtf(v0); v1 = roundtf(v1);
                v2 = roundtf(v2); v3 = roundtf(v3);
            }
            *(float2*)&C[(size_t)r0 * ldc + cc] = make_float2(v0, v1);
            *(float2*)&C[(size_t)r1 * ldc + cc] = make_float2(v2, v3);
        }
    }
}

// ------------------------------------------------------------ RoPE split ---
// q,k,v consumed as bf16 by attention; store plain f32 (single rounding later)
__global__ void rope_kernel(const float* __restrict__ freqs)
{
    int idx = blockIdx.x * blockDim.x + threadIdx.x;
    if (idx >= BB * NN * HH * 32) return;
    int i = idx & 31;
    int h = (idx >> 5) & 7;
    int n = (idx >> 8) & 2047;
    int b = idx >> 19;

    float f = freqs[(b * NN + n) * 32 + i];
    float c = cosf(f), s = sinf(f);

    int base = (b * NN + n) * 1536 + h * 64;
    int ob   = ((b * HH + h) * NN + n) * 64 + 2 * i;

    float q1 = g_qkv[base + 2*i], q2 = g_qkv[base + 2*i + 1];
    g_q[ob]     = q1 * c - q2 * s;
    g_q[ob + 1] = q1 * s + q2 * c;

    float k1 = g_qkv[base + 512 + 2*i], k2 = g_qkv[base + 512 + 2*i + 1];
    g_k[ob]     = k1 * c - k2 * s;
    g_k[ob + 1] = k1 * s + k2 * c;

    g_v[ob]     = g_qkv[base + 1024 + 2*i];
    g_v[ob + 1] = g_qkv[base + 1024 + 2*i + 1];
}

// ---------------------------------------- bf16 tensor-core flash attention -
// 128 q per CTA, 8 warps x 16 q-rows, 64-key tiles, m16n8k16 bf16 mma.
// Q frags in regs; P stays in regs (S C-frag == PV A-frag layout for k16).
// Ks[key][dim-pairs], Vst[dim][key-pairs], row stride 36 words -> bank
// = (4g+tg) distinct across warp: conflict-free.
#define KSW 36

__global__ __launch_bounds__(256, 2) void attn_bf16()
{
    __shared__ uint32_t Ks[64 * KSW];
    __shared__ uint32_t Vst[64 * KSW];

    const int bh = blockIdx.y;
    const int q0 = blockIdx.x * 128;
    const float* __restrict__ Qg = g_q + (size_t)bh * NN * HDIM;
    const float* __restrict__ Kg = g_k + (size_t)bh * NN * HDIM;
    const float* __restrict__ Vg = g_v + (size_t)bh * NN * HDIM;

    const int tid  = threadIdx.x;
    const int w    = tid >> 5;
    const int lane = tid & 31;
    const int g    = lane >> 2;
    const int tg   = lane & 3;
    const int w16  = w * 16;

    // ---- Q fragments to registers (A of m16n8k16, rows w16+g / +8) ----
    uint32_t qa[4][4];
    {
        const int r0 = q0 + w16 + g, r1 = r0 + 8;
        #pragma unroll
        for (int ks = 0; ks < 4; ks++) {
            const int d = ks * 16 + tg * 2;
            float2 v0 = *(const float2*)&Qg[(size_t)r0 * 64 + d];
            float2 v1 = *(const float2*)&Qg[(size_t)r1 * 64 + d];
            float2 v2 = *(const float2*)&Qg[(size_t)r0 * 64 + d + 8];
            float2 v3 = *(const float2*)&Qg[(size_t)r1 * 64 + d + 8];
            qa[ks][0] = pack_bf16(v0.x * 0.125f, v0.y * 0.125f);
            qa[ks][1] = pack_bf16(v1.x * 0.125f, v1.y * 0.125f);
            qa[ks][2] = pack_bf16(v2.x * 0.125f, v2.y * 0.125f);
            qa[ks][3] = pack_bf16(v3.x * 0.125f, v3.y * 0.125f);
        }
    }

    float m0 = -1e30f, m1 = -1e30f, l0 = 0.f, l1 = 0.f;
    float oacc[8][4];
    #pragma unroll
    for (int nt = 0; nt < 8; nt++)
        #pragma unroll
        for (int q = 0; q < 4; q++) oacc[nt][q] = 0.f;

    // fill mappings
    const int kr  = tid >> 2, kdq = (tid & 3) * 16;   // K: key row, dim chunk
    const int vp  = tid & 31, vdb = (tid >> 5) * 8;   // V: key pair, dim base

    for (int k0 = 0; k0 < NN; k0 += 64) {
        __syncthreads();
        // ---- K tile: [key][dim pairs] bf16 ----
        #pragma unroll
        for (int c = 0; c < 4; c++) {
            const int d = kdq + c * 4;
            float4 kv = *(const float4*)&Kg[(size_t)(k0 + kr) * 64 + d];
            uint2 u;
            u.x = pack_bf16(kv.x, kv.y);
            u.y = pack_bf16(kv.z, kv.w);
            *(uint2*)&Ks[kr * KSW + d / 2] = u;
        }
        // ---- V tile: transpose -> [dim][key pairs] bf16 ----
        #pragma unroll
        for (int c = 0; c < 2; c++) {
            const int d = vdb + c * 4;
            float4 a = *(const float4*)&Vg[(size_t)(k0 + 2 * vp) * 64 + d];
            float4 b = *(const float4*)&Vg[(size_t)(k0 + 2 * vp + 1) * 64 + d];
            Vst[(d + 0) * KSW + vp] = pack_bf16(a.x, b.x);
            Vst[(d + 1) * KSW + vp] = pack_bf16(a.y, b.y);
            Vst[(d + 2) * KSW + vp] = pack_bf16(a.z, b.z);
            Vst[(d + 3) * KSW + vp] = pack_bf16(a.w, b.w);
        }
        __syncthreads();

        // ---- S = Q K^T (4 k-steps of 16 dims) ----
        float sacc[8][4];
        #pragma unroll
        for (int nt = 0; nt < 8; nt++)
            #pragma unroll
            for (int q = 0; q < 4; q++) sacc[nt][q] = 0.f;

        #pragma unroll
        for (int ks = 0; ks < 4; ks++) {
            const int wb = ks * 8;
            #pragma unroll
            for (int nt = 0; nt < 8; nt++) {
                const uint32_t* row = &Ks[(nt * 8 + g) * KSW];
                mma_bf16(sacc[nt], qa[ks], row[wb + tg], row[wb + 4 + tg]);
            }
        }

        // ---- online softmax (rows g / g+8) ----
        float mt0 = -1e30f, mt1 = -1e30f;
        #pragma unroll
        for (int nt = 0; nt < 8; nt++) {
            mt0 = fmaxf(mt0, fmaxf(sacc[nt][0], sacc[nt][1]));
            mt1 = fmaxf(mt1, fmaxf(sacc[nt][2], sacc[nt][3]));
        }
        mt0 = fmaxf(mt0, __shfl_xor_sync(0xffffffffu, mt0, 1));
        mt0 = fmaxf(mt0, __shfl_xor_sync(0xffffffffu, mt0, 2));
        mt1 = fmaxf(mt1, __shfl_xor_sync(0xffffffffu, mt1, 1));
        mt1 = fmaxf(mt1, __shfl_xor_sync(0xffffffffu, mt1, 2));
        float mn0 = fmaxf(m0, mt0), mn1 = fmaxf(m1, mt1);

        float rs0 = 0.f, rs1 = 0.f;
        #pragma unroll
        for (int nt = 0; nt < 8; nt++) {
            sacc[nt][0] = __expf(sacc[nt][0] - mn0);
            sacc[nt][1] = __expf(sacc[nt][1] - mn0);
            sacc[nt][2] = __expf(sacc[nt][2] - mn1);
            sacc[nt][3] = __expf(sacc[nt][3] - mn1);
            rs0 += sacc[nt][0] + sacc[nt][1];
            rs1 += sacc[nt][2] + sacc[nt][3];
        }
        rs0 += __shfl_xor_sync(0xffffffffu, rs0, 1);
        rs0 += __shfl_xor_sync(0xffffffffu, rs0, 2);
        rs1 += __shfl_xor_sync(0xffffffffu, rs1, 1);
        rs1 += __shfl_xor_sync(0xffffffffu, rs1, 2);

        float c0 = __expf(m0 - mn0), c1 = __expf(m1 - mn1);
        l0 = l0 * c0 + rs0;  l1 = l1 * c1 + rs1;
        m0 = mn0;            m1 = mn1;
        #pragma unroll
        for (int nt = 0; nt < 8; nt++) {
            oacc[nt][0] *= c0; oacc[nt][1] *= c0;
            oacc[nt][2] *= c1; oacc[nt][3] *= c1;
        }

        // ---- P to bf16 A-frags (register-only; no smem round trip) ----
        uint32_t pa[8][2];
        #pragma unroll
        for (int nt = 0; nt < 8; nt++) {
            pa[nt][0] = pack_bf16(sacc[nt][0], sacc[nt][1]);   // row g
            pa[nt][1] = pack_bf16(sacc[nt][2], sacc[nt][3]);   // row g+8
        }

        // ---- O += P @ V (4 k-steps of 16 keys) ----
        #pragma unroll
        for (int ks = 0; ks < 4; ks++) {
            const int wb = ks * 8;
            uint32_t a[4] = { pa[2*ks][0], pa[2*ks][1],
                              pa[2*ks+1][0], pa[2*ks+1][1] };
            #pragma unroll
            for (int nt = 0; nt < 8; nt++) {
                const uint32_t* row = &Vst[(nt * 8 + g) * KSW];
                mma_bf16(oacc[nt], a, row[wb + tg], row[wb + 4 + tg]);
            }
        }
    }

    // ---- write out [B,N,D], tf32-rounded (feeds out-proj GEMM A) ----
    const int b = bh >> 3, h = bh & 7;
    const float inv0 = 1.f / l0, inv1 = 1.f / l1;
    const int r0 = q0 + w16 + g, r1 = r0 + 8;
    #pragma unroll
    for (int nt = 0; nt < 8; nt++) {
        int d = h * 64 + nt * 8 + tg * 2;
        *(float2*)&g_attn[(size_t)(b * NN + r0) * DD + d] =
            make_float2(roundtf(oacc[nt][0] * inv0), roundtf(oacc[nt][1] * inv0));
        *(float2*)&g_attn[(size_t)(b * NN + r1) * DD + d] =
            make_float2(roundtf(oacc[nt][2] * inv1), roundtf(oacc[nt][3] * inv1));
    }
}

// ------------------------------------------------------- LayerNorm + GELU --
__global__ __launch_bounds__(256) void ln_gelu_kernel(
    const float* __restrict__ gamma, const float* __restrict__ beta)
{
    const int r = blockIdx.x;
    const int t = threadIdx.x;
    float4 v = *(const float4*)&g_h1[(size_t)r * 1024 + t * 4];

    float sum = v.x + v.y + v.z + v.w;
    float sq  = v.x*v.x + v.y*v.y + v.z*v.z + v.w*v.w;
    #pragma unroll
    for (int off = 16; off >= 1; off >>= 1) {
        sum += __shfl_xor_sync(0xffffffffu, sum, off);
        sq  += __shfl_xor_sync(0xffffffffu, sq, off);
    }
    __shared__ float ssum[8], ssq[8];
    if ((t & 31) == 0) { ssum[t >> 5] = sum; ssq[t >> 5] = sq; }
    __syncthreads();
    float tot = 0.f, totq = 0.f;
    #pragma unroll
    for (int w = 0; w < 8; w++) { tot += ssum[w]; totq += ssq[w]; }

    float mean = tot * (1.f / 1024.f);
    float var  = totq * (1.f / 1024.f) - mean * mean;
    float inv  = rsqrtf(var + 1e-5f);

    float4 g4 = *(const float4*)&gamma[t * 4];
    float4 b4 = *(const float4*)&beta[t * 4];
    float y; float4 o;
    y = (v.x - mean) * inv * g4.x + b4.x; o.x = roundtf(0.5f * y * (1.f + erff(y * 0.70710678f)));
    y = (v.y - mean) * inv * g4.y + b4.y; o.y = roundtf(0.5f * y * (1.f + erff(y * 0.70710678f)));
    y = (v.z - mean) * inv * g4.z + b4.z; o.z = roundtf(0.5f * y * (1.f + erff(y * 0.70710678f)));
    y = (v.w - mean) * inv * g4.w + b4.w; o.w = roundtf(0.5f * y * (1.f + erff(y * 0.70710678f)));
    *(float4*)&g_h1[(size_t)r * 1024 + t * 4] = o;
}

// ------------------------------------------------------------- launcher ----
extern "C" void kernel_launch(void* const* d_in, const int* in_sizes, int n_in,
                              void* d_out, int out_size)
{
    const float* x      = (const float*)d_in[0];
    const float* freqs  = (const float*)d_in[1];
    const float* wqkv_w = (const float*)d_in[2];
    const float* wqkv_b = (const float*)d_in[3];
    const float* out_w  = (const float*)d_in[4];
    const float* out_b  = (const float*)d_in[5];
    const float* ffn1_w = (const float*)d_in[6];
    const float* ffn1_b = (const float*)d_in[7];
    const float* ln_g   = (const float*)d_in[8];
    const float* ln_b   = (const float*)d_in[9];
    const float* ffn2_w = (const float*)d_in[10];
    const float* ffn2_b = (const float*)d_in[11];
    float* out = (float*)d_out;

    float *p_qkv, *p_attn, *p_hcat, *p_h1, *p_xr, *p_wr;
    cudaGetSymbolAddress((void**)&p_qkv,  g_qkv);
    cudaGetSymbolAddress((void**)&p_attn, g_attn);
    cudaGetSymbolAddress((void**)&p_hcat, g_hcat);
    cudaGetSymbolAddress((void**)&p_h1,   g_h1);
    cudaGetSymbolAddress((void**)&p_xr,   g_xr);
    cudaGetSymbolAddress((void**)&p_wr,   g_wr);

    // 0. round x + all weights to tf32; also fill hcat[:,0:512]
    {
        int total_f4 = MROWS*DD/4 + (786432 + 262144 + 1048576 + 524288)/4;
        round_inputs<<<(total_f4 + 255)/256, 256>>>(x, wqkv_w, out_w, ffn1_w, ffn2_w);
    }

    // 1. QKV projection: [8192,512] @ [512,1536]
    gemm_tf32<<<dim3(1536/GBN, MROWS/GBM), 256>>>(
        p_xr, DD, p_wr + WOFF_QKV, 1536, p_qkv, 1536, wqkv_b, nullptr, 0, DD, 0);

    // 2. RoPE + head split
    rope_kernel<<<(BB*NN*HH*32 + 255)/256, 256>>>(freqs);

    // 3. Attention (bf16 m16n8k16 mma, register-resident P)
    attn_bf16<<<dim3(NN/128, BB*HH), 256>>>();

    // 4. out-proj into hcat right half (rounded): [8192,512]@[512,512]
    gemm_tf32<<<dim3(512/GBN, MROWS/GBM), 256>>>(
        p_attn, DD, p_wr + WOFF_OUT, DD, p_hcat + 512, 1024, out_b, nullptr, 0, DD, 1);

    // 5. FFN1: [8192,1024]@[1024,1024]
    gemm_tf32<<<dim3(1024/GBN, MROWS/GBM), 256>>>(
        p_hcat, 1024, p_wr + WOFF_FFN1, 1024, p_h1, 1024, ffn1_b, nullptr, 0, 1024, 0);

    // 6. LayerNorm + exact GELU (in place, stores rounded)
    ln_gelu_kernel<<<MROWS, 256>>>(ln_g, ln_b);

    // 7. FFN2 + residual: out = x + h1 @ [1024,512] + b
    gemm_tf32<<<dim3(512/GBN, MROWS/GBM), 256>>>(
        p_h1, 1024, p_wr + WOFF_FFN2, DD, out, DD, ffn2_b, x, DD, 1024, 0);
}

// round 8
// speedup vs baseline: 1.3033x; 1.0188x over previous
#include <cuda_runtime.h>
#include <cuda_bf16.h>
#include <math.h>
#include <stdint.h>

// Problem constants
#define BB 4
#define NN 2048
#define DD 512
#define HH 8
#define HDIM 64
#define MROWS (BB*NN)          // 8192

// ---------------- scratch (static device globals; no runtime allocation) ---
__device__ float g_qkv[MROWS*1536];
__device__ float g_q[MROWS*DD];
__device__ float g_k[MROWS*DD];
__device__ float g_v[MROWS*DD];
__device__ float g_attn[MROWS*DD];
__device__ float g_hcat[MROWS*1024];
__device__ float g_h1[MROWS*1024];
__device__ float g_xr[MROWS*DD];          // tf32-rounded x
__device__ float g_wr[2621440];           // tf32-rounded weights (all 4)

#define WOFF_QKV  0
#define WOFF_OUT  786432
#define WOFF_FFN1 1048576
#define WOFF_FFN2 2097152

// ------------------------------------------------------------ tf32 utils ---
__device__ __forceinline__ uint32_t f2tf32(float x) {
    uint32_t u;
    asm volatile("cvt.rna.tf32.f32 %0, %1;" : "=r"(u) : "f"(x));
    return u;
}
__device__ __forceinline__ float roundtf(float x) {
    return __uint_as_float(f2tf32(x));
}
// pack two f32 -> bf16x2 (lo = a, hi = b)
__device__ __forceinline__ uint32_t pack_bf16(float a, float b) {
    uint32_t r;
    asm("cvt.rn.bf16x2.f32 %0, %1, %2;" : "=r"(r) : "f"(b), "f"(a));
    return r;
}

__device__ __forceinline__ void mma_tf32(float c[4],
                                         const uint32_t a[4],
                                         const uint32_t b[2]) {
    asm volatile(
        "mma.sync.aligned.m16n8k8.row.col.f32.tf32.tf32.f32 "
        "{%0,%1,%2,%3}, {%4,%5,%6,%7}, {%8,%9}, {%0,%1,%2,%3};\n"
        : "+f"(c[0]), "+f"(c[1]), "+f"(c[2]), "+f"(c[3])
        : "r"(a[0]), "r"(a[1]), "r"(a[2]), "r"(a[3]),
          "r"(b[0]), "r"(b[1]));
}

__device__ __forceinline__ void mma_bf16(float c[4],
                                         const uint32_t a[4],
                                         uint32_t b0, uint32_t b1) {
    asm volatile(
        "mma.sync.aligned.m16n8k16.row.col.f32.bf16.bf16.f32 "
        "{%0,%1,%2,%3}, {%4,%5,%6,%7}, {%8,%9}, {%0,%1,%2,%3};\n"
        : "+f"(c[0]), "+f"(c[1]), "+f"(c[2]), "+f"(c[3])
        : "r"(a[0]), "r"(a[1]), "r"(a[2]), "r"(a[3]),
          "r"(b0), "r"(b1));
}

__device__ __forceinline__ void cp_async16(uint32_t saddr, const void* gptr) {
    asm volatile("cp.async.cg.shared.global [%0], [%1], 16;\n"
                 :: "r"(saddr), "l"(gptr));
}
#define CP_COMMIT() asm volatile("cp.async.commit_group;\n" ::: "memory")
#define CP_WAIT2()  asm volatile("cp.async.wait_group 2;\n" ::: "memory")

// --------------------------- pre-round x + weights, and fill hcat left half
__global__ __launch_bounds__(256) void round_inputs(
    const float* __restrict__ x,
    const float* __restrict__ w_qkv,
    const float* __restrict__ w_out,
    const float* __restrict__ w_ffn1,
    const float* __restrict__ w_ffn2)
{
    int idx = blockIdx.x * blockDim.x + threadIdx.x;  // float4 index
    const int nx = MROWS*DD/4;
    const int n0 = 786432/4;
    const int n1 = 262144/4;
    const int n2 = 1048576/4;
    const int n3 = 524288/4;
    if (idx < nx) {
        float4 v = ((const float4*)x)[idx];
        v.x = roundtf(v.x); v.y = roundtf(v.y);
        v.z = roundtf(v.z); v.w = roundtf(v.w);
        ((float4*)g_xr)[idx] = v;
        int m = idx >> 7, j = idx & 127;
        ((float4*)g_hcat)[m * 256 + j] = v;   // hcat[:, 0:512] = round(x)
        return;
    }
    int t = idx - nx;
    const float4* src; float4* dst;
    if (t < n0)                 { src = (const float4*)w_qkv + t;  dst = (float4*)(g_wr + WOFF_QKV) + t; }
    else if ((t -= n0) < n1)    { src = (const float4*)w_out + t;  dst = (float4*)(g_wr + WOFF_OUT) + t; }
    else if ((t -= n1) < n2)    { src = (const float4*)w_ffn1 + t; dst = (float4*)(g_wr + WOFF_FFN1) + t; }
    else if ((t -= n2) < n3)    { src = (const float4*)w_ffn2 + t; dst = (float4*)(g_wr + WOFF_FFN2) + t; }
    else return;
    float4 v = *src;
    v.x = roundtf(v.x); v.y = roundtf(v.y);
    v.z = roundtf(v.z); v.w = roundtf(v.w);
    *dst = v;
}

// --------------------------------------- 4-stage pipelined tf32 GEMM -------
// Operands pre-rounded to tf32 bit patterns (in-mma truncation exact).
#define GBM 128
#define GBN 128
#define GBK 16
#define APADW 20
#define BPADW 136
#define STAGE_W (GBM*APADW + GBK*BPADW)       // 4736 words
#define STAGE_B (STAGE_W*4)                   // 18944 bytes
#define GEMM_SMEM (4*STAGE_B)                 // 75776 bytes

__global__ __launch_bounds__(256) void gemm_tf32(
    const float* __restrict__ A, int lda,
    const float* __restrict__ Bm, int ldb,
    float* __restrict__ C, int ldc,
    const float* __restrict__ bias,
    const float* __restrict__ res, int ldres,
    int K, int roundC)
{
    extern __shared__ uint32_t gsm[];
    const uint32_t sbase = (uint32_t)__cvta_generic_to_shared(gsm);

    const int tid  = threadIdx.x;
    const int brow = blockIdx.y * GBM;
    const int bcol = blockIdx.x * GBN;
    const int w    = tid >> 5;
    const int lane = tid & 31;
    const int g    = lane >> 2;
    const int tg   = lane & 3;
    const int wm   = (w & 1) * 64;
    const int wn   = (w >> 1) * 32;

    // per-thread load coords
    const int ar0 = tid >> 2,  ac0 = (tid & 3) * 4;
    const int ar1 = ar0 + 64;
    const int bk0 = tid >> 5,  bn0 = (tid & 31) * 4;
    const int bk1 = bk0 + 8;
    const uint32_t offA0 = (uint32_t)(ar0 * APADW + ac0) * 4;
    const uint32_t offA1 = (uint32_t)(ar1 * APADW + ac0) * 4;
    const uint32_t offB0 = (uint32_t)(GBM * APADW + bk0 * BPADW + bn0) * 4;
    const uint32_t offB1 = (uint32_t)(GBM * APADW + bk1 * BPADW + bn0) * 4;

    const float* gA0 = &A[(size_t)(brow + ar0) * lda + ac0];
    const float* gA1 = &A[(size_t)(brow + ar1) * lda + ac0];
    const float* gB0 = &Bm[(size_t)bk0 * ldb + bcol + bn0];
    const float* gB1 = &Bm[(size_t)bk1 * ldb + bcol + bn0];

    float acc[4][4][4];
    #pragma unroll
    for (int mi = 0; mi < 4; mi++)
        #pragma unroll
        for (int ni = 0; ni < 4; ni++)
            #pragma unroll
            for (int q = 0; q < 4; q++) acc[mi][ni][q] = 0.f;

    const int nk = K / GBK;   // >= 32 always here

    // prologue: stages 0,1,2 in flight
    #pragma unroll
    for (int s = 0; s < 3; s++) {
        const uint32_t sb = sbase + s * STAGE_B;
        const int k0 = s * GBK;
        cp_async16(sb + offA0, gA0 + k0);
        cp_async16(sb + offA1, gA1 + k0);
        cp_async16(sb + offB0, gB0 + (size_t)k0 * ldb);
        cp_async16(sb + offB1, gB1 + (size_t)k0 * ldb);
        CP_COMMIT();
    }

    for (int kt = 0; kt < nk; kt++) {
        // invariant: committed groups = 3 + kt  ->  wait<=2 pending
        // guarantees stages 0..kt complete.
        CP_WAIT2();
        __syncthreads();
        // refill stage (kt+3)%4 (its previous contents were consumed at kt-1)
        if (kt + 3 < nk) {
            const uint32_t sb = sbase + ((kt + 3) & 3) * STAGE_B;
            const int k0 = (kt + 3) * GBK;
            cp_async16(sb + offA0, gA0 + k0);
            cp_async16(sb + offA1, gA1 + k0);
            cp_async16(sb + offB0, gB0 + (size_t)k0 * ldb);
            cp_async16(sb + offB1, gB1 + (size_t)k0 * ldb);
        }
        CP_COMMIT();   // always commit: keeps the invariant

        const uint32_t* Asb = gsm + (kt & 3) * STAGE_W;
        const uint32_t* Bsb = Asb + GBM * APADW;

        #pragma unroll
        for (int ks = 0; ks < 2; ks++) {
            const int kk = ks * 8;
            uint32_t af[4][4], bf[4][2];
            #pragma unroll
            for (int mi = 0; mi < 4; mi++) {
                int r = wm + mi * 16 + g;
                af[mi][0] = Asb[r * APADW + kk + tg];
                af[mi][1] = Asb[(r + 8) * APADW + kk + tg];
                af[mi][2] = Asb[r * APADW + kk + tg + 4];
                af[mi][3] = Asb[(r + 8) * APADW + kk + tg + 4];
            }
            #pragma unroll
            for (int ni = 0; ni < 4; ni++) {
                int cc = wn + ni * 8 + g;
                bf[ni][0] = Bsb[(kk + tg) * BPADW + cc];
                bf[ni][1] = Bsb[(kk + tg + 4) * BPADW + cc];
            }
            #pragma unroll
            for (int mi = 0; mi < 4; mi++)
                #pragma unroll
                for (int ni = 0; ni < 4; ni++)
                    mma_tf32(acc[mi][ni], af[mi], bf[ni]);
        }
    }

    #pragma unroll
    for (int mi = 0; mi < 4; mi++) {
        int r0 = brow + wm + mi * 16 + g;
        int r1 = r0 + 8;
        #pragma unroll
        for (int ni = 0; ni < 4; ni++) {
            int cc = bcol + wn + ni * 8 + tg * 2;
            float2 b2 = *(const float2*)&bias[cc];
            float v0 = acc[mi][ni][0] + b2.x;
            float v1 = acc[mi][ni][1] + b2.y;
            float v2 = acc[mi][ni][2] + b2.x;
            float v3 = acc[mi][ni][3] + b2.y;
            if (res) {
                float2 ra = *(const float2*)&res[(size_t)r0 * ldres + cc];
                float2 rb = *(const float2*)&res[(size_t)r1 * ldres + cc];
                v0 += ra.x; v1 += ra.y; v2 += rb.x; v3 += rb.y;
            }
            if (roundC) {
                v0 = roundtf(v0); v1 = roundtf(v1);
                v2 = roundtf(v2); v3 = roundtf(v3);
            }
            *(float2*)&C[(size_t)r0 * ldc + cc] = make_float2(v0, v1);
            *(float2*)&C[(size_t)r1 * ldc + cc] = make_float2(v2, v3);
        }
    }
}

// ------------------------------------------------------------ RoPE split ---
__global__ void rope_kernel(const float* __restrict__ freqs)
{
    int idx = blockIdx.x * blockDim.x + threadIdx.x;
    if (idx >= BB * NN * HH * 32) return;
    int i = idx & 31;
    int h = (idx >> 5) & 7;
    int n = (idx >> 8) & 2047;
    int b = idx >> 19;

    float f = freqs[(b * NN + n) * 32 + i];
    float c = cosf(f), s = sinf(f);

    int base = (b * NN + n) * 1536 + h * 64;
    int ob   = ((b * HH + h) * NN + n) * 64 + 2 * i;

    float q1 = g_qkv[base + 2*i], q2 = g_qkv[base + 2*i + 1];
    g_q[ob]     = q1 * c - q2 * s;
    g_q[ob + 1] = q1 * s + q2 * c;

    float k1 = g_qkv[base + 512 + 2*i], k2 = g_qkv[base + 512 + 2*i + 1];
    g_k[ob]     = k1 * c - k2 * s;
    g_k[ob + 1] = k1 * s + k2 * c;

    g_v[ob]     = g_qkv[base + 1024 + 2*i];
    g_v[ob + 1] = g_qkv[base + 1024 + 2*i + 1];
}

// ---------------------------------------- bf16 tensor-core flash attention -
// (R7 winner, unchanged)
#define KSW 36

__global__ __launch_bounds__(256, 2) void attn_bf16()
{
    __shared__ uint32_t Ks[64 * KSW];
    __shared__ uint32_t Vst[64 * KSW];

    const int bh = blockIdx.y;
    const int q0 = blockIdx.x * 128;
    const float* __restrict__ Qg = g_q + (size_t)bh * NN * HDIM;
    const float* __restrict__ Kg = g_k + (size_t)bh * NN * HDIM;
    const float* __restrict__ Vg = g_v + (size_t)bh * NN * HDIM;

    const int tid  = threadIdx.x;
    const int w    = tid >> 5;
    const int lane = tid & 31;
    const int g    = lane >> 2;
    const int tg   = lane & 3;
    const int w16  = w * 16;

    uint32_t qa[4][4];
    {
        const int r0 = q0 + w16 + g, r1 = r0 + 8;
        #pragma unroll
        for (int ks = 0; ks < 4; ks++) {
            const int d = ks * 16 + tg * 2;
            float2 v0 = *(const float2*)&Qg[(size_t)r0 * 64 + d];
            float2 v1 = *(const float2*)&Qg[(size_t)r1 * 64 + d];
            float2 v2 = *(const float2*)&Qg[(size_t)r0 * 64 + d + 8];
            float2 v3 = *(const float2*)&Qg[(size_t)r1 * 64 + d + 8];
            qa[ks][0] = pack_bf16(v0.x * 0.125f, v0.y * 0.125f);
            qa[ks][1] = pack_bf16(v1.x * 0.125f, v1.y * 0.125f);
            qa[ks][2] = pack_bf16(v2.x * 0.125f, v2.y * 0.125f);
            qa[ks][3] = pack_bf16(v3.x * 0.125f, v3.y * 0.125f);
        }
    }

    float m0 = -1e30f, m1 = -1e30f, l0 = 0.f, l1 = 0.f;
    float oacc[8][4];
    #pragma unroll
    for (int nt = 0; nt < 8; nt++)
        #pragma unroll
        for (int q = 0; q < 4; q++) oacc[nt][q] = 0.f;

    const int kr  = tid >> 2, kdq = (tid & 3) * 16;
    const int vp  = tid & 31, vdb = (tid >> 5) * 8;

    for (int k0 = 0; k0 < NN; k0 += 64) {
        __syncthreads();
        #pragma unroll
        for (int c = 0; c < 4; c++) {
            const int d = kdq + c * 4;
            float4 kv = *(const float4*)&Kg[(size_t)(k0 + kr) * 64 + d];
            uint2 u;
            u.x = pack_bf16(kv.x, kv.y);
            u.y = pack_bf16(kv.z, kv.w);
            *(uint2*)&Ks[kr * KSW + d / 2] = u;
        }
        #pragma unroll
        for (int c = 0; c < 2; c++) {
            const int d = vdb + c * 4;
            float4 a = *(const float4*)&Vg[(size_t)(k0 + 2 * vp) * 64 + d];
            float4 b = *(const float4*)&Vg[(size_t)(k0 + 2 * vp + 1) * 64 + d];
            Vst[(d + 0) * KSW + vp] = pack_bf16(a.x, b.x);
            Vst[(d + 1) * KSW + vp] = pack_bf16(a.y, b.y);
            Vst[(d + 2) * KSW + vp] = pack_bf16(a.z, b.z);
            Vst[(d + 3) * KSW + vp] = pack_bf16(a.w, b.w);
        }
        __syncthreads();

        float sacc[8][4];
        #pragma unroll
        for (int nt = 0; nt < 8; nt++)
            #pragma unroll
            for (int q = 0; q < 4; q++) sacc[nt][q] = 0.f;

        #pragma unroll
        for (int ks = 0; ks < 4; ks++) {
            const int wb = ks * 8;
            #pragma unroll
            for (int nt = 0; nt < 8; nt++) {
                const uint32_t* row = &Ks[(nt * 8 + g) * KSW];
                mma_bf16(sacc[nt], qa[ks], row[wb + tg], row[wb + 4 + tg]);
            }
        }

        float mt0 = -1e30f, mt1 = -1e30f;
        #pragma unroll
        for (int nt = 0; nt < 8; nt++) {
            mt0 = fmaxf(mt0, fmaxf(sacc[nt][0], sacc[nt][1]));
            mt1 = fmaxf(mt1, fmaxf(sacc[nt][2], sacc[nt][3]));
        }
        mt0 = fmaxf(mt0, __shfl_xor_sync(0xffffffffu, mt0, 1));
        mt0 = fmaxf(mt0, __shfl_xor_sync(0xffffffffu, mt0, 2));
        mt1 = fmaxf(mt1, __shfl_xor_sync(0xffffffffu, mt1, 1));
        mt1 = fmaxf(mt1, __shfl_xor_sync(0xffffffffu, mt1, 2));
        float mn0 = fmaxf(m0, mt0), mn1 = fmaxf(m1, mt1);

        float rs0 = 0.f, rs1 = 0.f;
        #pragma unroll
        for (int nt = 0; nt < 8; nt++) {
            sacc[nt][0] = __expf(sacc[nt][0] - mn0);
            sacc[nt][1] = __expf(sacc[nt][1] - mn0);
            sacc[nt][2] = __expf(sacc[nt][2] - mn1);
            sacc[nt][3] = __expf(sacc[nt][3] - mn1);
            rs0 += sacc[nt][0] + sacc[nt][1];
            rs1 += sacc[nt][2] + sacc[nt][3];
        }
        rs0 += __shfl_xor_sync(0xffffffffu, rs0, 1);
        rs0 += __shfl_xor_sync(0xffffffffu, rs0, 2);
        rs1 += __shfl_xor_sync(0xffffffffu, rs1, 1);
        rs1 += __shfl_xor_sync(0xffffffffu, rs1, 2);

        float c0 = __expf(m0 - mn0), c1 = __expf(m1 - mn1);
        l0 = l0 * c0 + rs0;  l1 = l1 * c1 + rs1;
        m0 = mn0;            m1 = mn1;
        #pragma unroll
        for (int nt = 0; nt < 8; nt++) {
            oacc[nt][0] *= c0; oacc[nt][1] *= c0;
            oacc[nt][2] *= c1; oacc[nt][3] *= c1;
        }

        uint32_t pa[8][2];
        #pragma unroll
        for (int nt = 0; nt < 8; nt++) {
            pa[nt][0] = pack_bf16(sacc[nt][0], sacc[nt][1]);
            pa[nt][1] = pack_bf16(sacc[nt][2], sacc[nt][3]);
        }

        #pragma unroll
        for (int ks = 0; ks < 4; ks++) {
            const int wb = ks * 8;
            uint32_t a[4] = { pa[2*ks][0], pa[2*ks][1],
                              pa[2*ks+1][0], pa[2*ks+1][1] };
            #pragma unroll
            for (int nt = 0; nt < 8; nt++) {
                const uint32_t* row = &Vst[(nt * 8 + g) * KSW];
                mma_bf16(oacc[nt], a, row[wb + tg], row[wb + 4 + tg]);
            }
        }
    }

    const int b = bh >> 3, h = bh & 7;
    const float inv0 = 1.f / l0, inv1 = 1.f / l1;
    const int r0 = q0 + w16 + g, r1 = r0 + 8;
    #pragma unroll
    for (int nt = 0; nt < 8; nt++) {
        int d = h * 64 + nt * 8 + tg * 2;
        *(float2*)&g_attn[(size_t)(b * NN + r0) * DD + d] =
            make_float2(roundtf(oacc[nt][0] * inv0), roundtf(oacc[nt][1] * inv0));
        *(float2*)&g_attn[(size_t)(b * NN + r1) * DD + d] =
            make_float2(roundtf(oacc[nt][2] * inv1), roundtf(oacc[nt][3] * inv1));
    }
}

// ------------------------------------------------------- LayerNorm + GELU --
__global__ __launch_bounds__(256) void ln_gelu_kernel(
    const float* __restrict__ gamma, const float* __restrict__ beta)
{
    const int r = blockIdx.x;
    const int t = threadIdx.x;
    float4 v = *(const float4*)&g_h1[(size_t)r * 1024 + t * 4];

    float sum = v.x + v.y + v.z + v.w;
    float sq  = v.x*v.x + v.y*v.y + v.z*v.z + v.w*v.w;
    #pragma unroll
    for (int off = 16; off >= 1; off >>= 1) {
        sum += __shfl_xor_sync(0xffffffffu, sum, off);
        sq  += __shfl_xor_sync(0xffffffffu, sq, off);
    }
    __shared__ float ssum[8], ssq[8];
    if ((t & 31) == 0) { ssum[t >> 5] = sum; ssq[t >> 5] = sq; }
    __syncthreads();
    float tot = 0.f, totq = 0.f;
    #pragma unroll
    for (int w = 0; w < 8; w++) { tot += ssum[w]; totq += ssq[w]; }

    float mean = tot * (1.f / 1024.f);
    float var  = totq * (1.f / 1024.f) - mean * mean;
    float inv  = rsqrtf(var + 1e-5f);

    float4 g4 = *(const float4*)&gamma[t * 4];
    float4 b4 = *(const float4*)&beta[t * 4];
    float y; float4 o;
    y = (v.x - mean) * inv * g4.x + b4.x; o.x = roundtf(0.5f * y * (1.f + erff(y * 0.70710678f)));
    y = (v.y - mean) * inv * g4.y + b4.y; o.y = roundtf(0.5f * y * (1.f + erff(y * 0.70710678f)));
    y = (v.z - mean) * inv * g4.z + b4.z; o.z = roundtf(0.5f * y * (1.f + erff(y * 0.70710678f)));
    y = (v.w - mean) * inv * g4.w + b4.w; o.w = roundtf(0.5f * y * (1.f + erff(y * 0.70710678f)));
    *(float4*)&g_h1[(size_t)r * 1024 + t * 4] = o;
}

// ------------------------------------------------------------- launcher ----
extern "C" void kernel_launch(void* const* d_in, const int* in_sizes, int n_in,
                              void* d_out, int out_size)
{
    const float* x      = (const float*)d_in[0];
    const float* freqs  = (const float*)d_in[1];
    const float* wqkv_w = (const float*)d_in[2];
    const float* wqkv_b = (const float*)d_in[3];
    const float* out_w  = (const float*)d_in[4];
    const float* out_b  = (const float*)d_in[5];
    const float* ffn1_w = (const float*)d_in[6];
    const float* ffn1_b = (const float*)d_in[7];
    const float* ln_g   = (const float*)d_in[8];
    const float* ln_b   = (const float*)d_in[9];
    const float* ffn2_w = (const float*)d_in[10];
    const float* ffn2_b = (const float*)d_in[11];
    float* out = (float*)d_out;

    float *p_qkv, *p_attn, *p_hcat, *p_h1, *p_xr, *p_wr;
    cudaGetSymbolAddress((void**)&p_qkv,  g_qkv);
    cudaGetSymbolAddress((void**)&p_attn, g_attn);
    cudaGetSymbolAddress((void**)&p_hcat, g_hcat);
    cudaGetSymbolAddress((void**)&p_h1,   g_h1);
    cudaGetSymbolAddress((void**)&p_xr,   g_xr);
    cudaGetSymbolAddress((void**)&p_wr,   g_wr);

    cudaFuncSetAttribute(gemm_tf32,
                         cudaFuncAttributeMaxDynamicSharedMemorySize, GEMM_SMEM);

    // 0. round x + all weights to tf32; also fill hcat[:,0:512]
    {
        int total_f4 = MROWS*DD/4 + (786432 + 262144 + 1048576 + 524288)/4;
        round_inputs<<<(total_f4 + 255)/256, 256>>>(x, wqkv_w, out_w, ffn1_w, ffn2_w);
    }

    // 1. QKV projection: [8192,512] @ [512,1536]
    gemm_tf32<<<dim3(1536/GBN, MROWS/GBM), 256, GEMM_SMEM>>>(
        p_xr, DD, p_wr + WOFF_QKV, 1536, p_qkv, 1536, wqkv_b, nullptr, 0, DD, 0);

    // 2. RoPE + head split
    rope_kernel<<<(BB*NN*HH*32 + 255)/256, 256>>>(freqs);

    // 3. Attention (bf16 m16n8k16 mma, register-resident P)
    attn_bf16<<<dim3(NN/128, BB*HH), 256>>>();

    // 4. out-proj into hcat right half (rounded): [8192,512]@[512,512]
    gemm_tf32<<<dim3(512/GBN, MROWS/GBM), 256, GEMM_SMEM>>>(
        p_attn, DD, p_wr + WOFF_OUT, DD, p_hcat + 512, 1024, out_b, nullptr, 0, DD, 1);

    // 5. FFN1: [8192,1024]@[1024,1024]
    gemm_tf32<<<dim3(1024/GBN, MROWS/GBM), 256, GEMM_SMEM>>>(
        p_hcat, 1024, p_wr + WOFF_FFN1, 1024, p_h1, 1024, ffn1_b, nullptr, 0, 1024, 0);

    // 6. LayerNorm + exact GELU (in place, stores rounded)
    ln_gelu_kernel<<<MROWS, 256>>>(ln_g, ln_b);

    // 7. FFN2 + residual: out = x + h1 @ [1024,512] + b
    gemm_tf32<<<dim3(512/GBN, MROWS/GBM), 256, GEMM_SMEM>>>(
        p_h1, 1024, p_wr + WOFF_FFN2, DD, out, DD, ffn2_b, x, DD, 1024, 0);
}

// round 9
// speedup vs baseline: 1.5393x; 1.1811x over previous
#include <cuda_runtime.h>
#include <cuda_bf16.h>
#include <math.h>
#include <stdint.h>

// Problem constants
#define BB 4
#define NN 2048
#define DD 512
#define HH 8
#define HDIM 64
#define MROWS (BB*NN)          // 8192

// ---------------- scratch (static device globals; no runtime allocation) ---
__device__ float g_qkv[MROWS*1536];
__device__ float g_attn[MROWS*DD];
__device__ float g_hcat[MROWS*1024];
__device__ float g_h1[MROWS*1024];
__device__ float g_xr[MROWS*DD];          // tf32-rounded x
__device__ float g_wr[2621440];           // tf32-rounded weights (all 4)
__device__ uint32_t g_qb[MROWS*256];      // bf16x2 Q [bh][n][d/2], pre-scaled
__device__ uint32_t g_kb[MROWS*256];      // bf16x2 K [bh][n][d/2]
__device__ uint32_t g_vtb[MROWS*256];     // bf16x2 V^T [bh][d][n/2]

#define WOFF_QKV  0
#define WOFF_OUT  786432
#define WOFF_FFN1 1048576
#define WOFF_FFN2 2097152

// ------------------------------------------------------------ tf32 utils ---
__device__ __forceinline__ uint32_t f2tf32(float x) {
    uint32_t u;
    asm volatile("cvt.rna.tf32.f32 %0, %1;" : "=r"(u) : "f"(x));
    return u;
}
__device__ __forceinline__ float roundtf(float x) {
    return __uint_as_float(f2tf32(x));
}
// pack two f32 -> bf16x2 (lo = a, hi = b)
__device__ __forceinline__ uint32_t pack_bf16(float a, float b) {
    uint32_t r;
    asm("cvt.rn.bf16x2.f32 %0, %1, %2;" : "=r"(r) : "f"(b), "f"(a));
    return r;
}

__device__ __forceinline__ void mma_tf32(float c[4],
                                         const uint32_t a[4],
                                         const uint32_t b[2]) {
    asm volatile(
        "mma.sync.aligned.m16n8k8.row.col.f32.tf32.tf32.f32 "
        "{%0,%1,%2,%3}, {%4,%5,%6,%7}, {%8,%9}, {%0,%1,%2,%3};\n"
        : "+f"(c[0]), "+f"(c[1]), "+f"(c[2]), "+f"(c[3])
        : "r"(a[0]), "r"(a[1]), "r"(a[2]), "r"(a[3]),
          "r"(b[0]), "r"(b[1]));
}

__device__ __forceinline__ void mma_bf16(float c[4],
                                         const uint32_t a[4],
                                         uint32_t b0, uint32_t b1) {
    asm volatile(
        "mma.sync.aligned.m16n8k16.row.col.f32.bf16.bf16.f32 "
        "{%0,%1,%2,%3}, {%4,%5,%6,%7}, {%8,%9}, {%0,%1,%2,%3};\n"
        : "+f"(c[0]), "+f"(c[1]), "+f"(c[2]), "+f"(c[3])
        : "r"(a[0]), "r"(a[1]), "r"(a[2]), "r"(a[3]),
          "r"(b0), "r"(b1));
}

__device__ __forceinline__ void cp_async16(uint32_t saddr, const void* gptr) {
    asm volatile("cp.async.cg.shared.global [%0], [%1], 16;\n"
                 :: "r"(saddr), "l"(gptr));
}
#define CP_COMMIT() asm volatile("cp.async.commit_group;\n" ::: "memory")
#define CP_WAIT1()  asm volatile("cp.async.wait_group 1;\n" ::: "memory")
#define CP_WAIT2()  asm volatile("cp.async.wait_group 2;\n" ::: "memory")

// --------------------------- pre-round x + weights, and fill hcat left half
__global__ __launch_bounds__(256) void round_inputs(
    const float* __restrict__ x,
    const float* __restrict__ w_qkv,
    const float* __restrict__ w_out,
    const float* __restrict__ w_ffn1,
    const float* __restrict__ w_ffn2)
{
    int idx = blockIdx.x * blockDim.x + threadIdx.x;  // float4 index
    const int nx = MROWS*DD/4;
    const int n0 = 786432/4;
    const int n1 = 262144/4;
    const int n2 = 1048576/4;
    const int n3 = 524288/4;
    if (idx < nx) {
        float4 v = ((const float4*)x)[idx];
        v.x = roundtf(v.x); v.y = roundtf(v.y);
        v.z = roundtf(v.z); v.w = roundtf(v.w);
        ((float4*)g_xr)[idx] = v;
        int m = idx >> 7, j = idx & 127;
        ((float4*)g_hcat)[m * 256 + j] = v;   // hcat[:, 0:512] = round(x)
        return;
    }
    int t = idx - nx;
    const float4* src; float4* dst;
    if (t < n0)                 { src = (const float4*)w_qkv + t;  dst = (float4*)(g_wr + WOFF_QKV) + t; }
    else if ((t -= n0) < n1)    { src = (const float4*)w_out + t;  dst = (float4*)(g_wr + WOFF_OUT) + t; }
    else if ((t -= n1) < n2)    { src = (const float4*)w_ffn1 + t; dst = (float4*)(g_wr + WOFF_FFN1) + t; }
    else if ((t -= n2) < n3)    { src = (const float4*)w_ffn2 + t; dst = (float4*)(g_wr + WOFF_FFN2) + t; }
    else return;
    float4 v = *src;
    v.x = roundtf(v.x); v.y = roundtf(v.y);
    v.z = roundtf(v.z); v.w = roundtf(v.w);
    *dst = v;
}

// --------------------------------------- 4-stage pipelined tf32 GEMM (R8) --
#define GBM 128
#define GBN 128
#define GBK 16
#define APADW 20
#define BPADW 136
#define STAGE_W (GBM*APADW + GBK*BPADW)       // 4736 words
#define STAGE_B (STAGE_W*4)
#define GEMM_SMEM (4*STAGE_B)                 // 75776 bytes

__global__ __launch_bounds__(256) void gemm_tf32(
    const float* __restrict__ A, int lda,
    const float* __restrict__ Bm, int ldb,
    float* __restrict__ C, int ldc,
    const float* __restrict__ bias,
    const float* __restrict__ res, int ldres,
    int K, int roundC)
{
    extern __shared__ uint32_t gsm[];
    const uint32_t sbase = (uint32_t)__cvta_generic_to_shared(gsm);

    const int tid  = threadIdx.x;
    const int brow = blockIdx.y * GBM;
    const int bcol = blockIdx.x * GBN;
    const int w    = tid >> 5;
    const int lane = tid & 31;
    const int g    = lane >> 2;
    const int tg   = lane & 3;
    const int wm   = (w & 1) * 64;
    const int wn   = (w >> 1) * 32;

    const int ar0 = tid >> 2,  ac0 = (tid & 3) * 4;
    const int ar1 = ar0 + 64;
    const int bk0 = tid >> 5,  bn0 = (tid & 31) * 4;
    const int bk1 = bk0 + 8;
    const uint32_t offA0 = (uint32_t)(ar0 * APADW + ac0) * 4;
    const uint32_t offA1 = (uint32_t)(ar1 * APADW + ac0) * 4;
    const uint32_t offB0 = (uint32_t)(GBM * APADW + bk0 * BPADW + bn0) * 4;
    const uint32_t offB1 = (uint32_t)(GBM * APADW + bk1 * BPADW + bn0) * 4;

    const float* gA0 = &A[(size_t)(brow + ar0) * lda + ac0];
    const float* gA1 = &A[(size_t)(brow + ar1) * lda + ac0];
    const float* gB0 = &Bm[(size_t)bk0 * ldb + bcol + bn0];
    const float* gB1 = &Bm[(size_t)bk1 * ldb + bcol + bn0];

    float acc[4][4][4];
    #pragma unroll
    for (int mi = 0; mi < 4; mi++)
        #pragma unroll
        for (int ni = 0; ni < 4; ni++)
            #pragma unroll
            for (int q = 0; q < 4; q++) acc[mi][ni][q] = 0.f;

    const int nk = K / GBK;

    #pragma unroll
    for (int s = 0; s < 3; s++) {
        const uint32_t sb = sbase + s * STAGE_B;
        const int k0 = s * GBK;
        cp_async16(sb + offA0, gA0 + k0);
        cp_async16(sb + offA1, gA1 + k0);
        cp_async16(sb + offB0, gB0 + (size_t)k0 * ldb);
        cp_async16(sb + offB1, gB1 + (size_t)k0 * ldb);
        CP_COMMIT();
    }

    for (int kt = 0; kt < nk; kt++) {
        CP_WAIT2();
        __syncthreads();
        if (kt + 3 < nk) {
            const uint32_t sb = sbase + ((kt + 3) & 3) * STAGE_B;
            const int k0 = (kt + 3) * GBK;
            cp_async16(sb + offA0, gA0 + k0);
            cp_async16(sb + offA1, gA1 + k0);
            cp_async16(sb + offB0, gB0 + (size_t)k0 * ldb);
            cp_async16(sb + offB1, gB1 + (size_t)k0 * ldb);
        }
        CP_COMMIT();

        const uint32_t* Asb = gsm + (kt & 3) * STAGE_W;
        const uint32_t* Bsb = Asb + GBM * APADW;

        #pragma unroll
        for (int ks = 0; ks < 2; ks++) {
            const int kk = ks * 8;
            uint32_t af[4][4], bf[4][2];
            #pragma unroll
            for (int mi = 0; mi < 4; mi++) {
                int r = wm + mi * 16 + g;
                af[mi][0] = Asb[r * APADW + kk + tg];
                af[mi][1] = Asb[(r + 8) * APADW + kk + tg];
                af[mi][2] = Asb[r * APADW + kk + tg + 4];
                af[mi][3] = Asb[(r + 8) * APADW + kk + tg + 4];
            }
            #pragma unroll
            for (int ni = 0; ni < 4; ni++) {
                int cc = wn + ni * 8 + g;
                bf[ni][0] = Bsb[(kk + tg) * BPADW + cc];
                bf[ni][1] = Bsb[(kk + tg + 4) * BPADW + cc];
            }
            #pragma unroll
            for (int mi = 0; mi < 4; mi++)
                #pragma unroll
                for (int ni = 0; ni < 4; ni++)
                    mma_tf32(acc[mi][ni], af[mi], bf[ni]);
        }
    }

    #pragma unroll
    for (int mi = 0; mi < 4; mi++) {
        int r0 = brow + wm + mi * 16 + g;
        int r1 = r0 + 8;
        #pragma unroll
        for (int ni = 0; ni < 4; ni++) {
            int cc = bcol + wn + ni * 8 + tg * 2;
            float2 b2 = *(const float2*)&bias[cc];
            float v0 = acc[mi][ni][0] + b2.x;
            float v1 = acc[mi][ni][1] + b2.y;
            float v2 = acc[mi][ni][2] + b2.x;
            float v3 = acc[mi][ni][3] + b2.y;
            if (res) {
                float2 ra = *(const float2*)&res[(size_t)r0 * ldres + cc];
                float2 rb = *(const float2*)&res[(size_t)r1 * ldres + cc];
                v0 += ra.x; v1 += ra.y; v2 += rb.x; v3 += rb.y;
            }
            if (roundC) {
                v0 = roundtf(v0); v1 = roundtf(v1);
                v2 = roundtf(v2); v3 = roundtf(v3);
            }
            *(float2*)&C[(size_t)r0 * ldc + cc] = make_float2(v0, v1);
            *(float2*)&C[(size_t)r1 * ldc + cc] = make_float2(v2, v3);
        }
    }
}

// ------------------------------------------------------------ RoPE split ---
// Writes Q (pre-scaled 1/8) and K as packed bf16x2 into [bh][n][d/2].
__global__ void rope_kernel(const float* __restrict__ freqs)
{
    int idx = blockIdx.x * blockDim.x + threadIdx.x;
    if (idx >= BB * NN * HH * 32) return;
    int i = idx & 31;
    int h = (idx >> 5) & 7;
    int n = (idx >> 8) & 2047;
    int b = idx >> 19;

    float f = freqs[(b * NN + n) * 32 + i];
    float c = cosf(f), s = sinf(f);

    int base = (b * NN + n) * 1536 + h * 64;
    int ow   = ((b * HH + h) * NN + n) * 32 + i;

    float q1 = g_qkv[base + 2*i], q2 = g_qkv[base + 2*i + 1];
    g_qb[ow] = pack_bf16((q1 * c - q2 * s) * 0.125f,
                         (q1 * s + q2 * c) * 0.125f);

    float k1 = g_qkv[base + 512 + 2*i], k2 = g_qkv[base + 512 + 2*i + 1];
    g_kb[ow] = pack_bf16(k1 * c - k2 * s, k1 * s + k2 * c);
}

// ----------------------------------------------- V transpose to bf16x2 -----
// g_qkv V section [n][d] -> g_vtb [bh][d][n/2] (word packs tokens 2p,2p+1)
__global__ __launch_bounds__(128) void vtrans_kernel()
{
    __shared__ float ts[64 * 65];
    const int bh = blockIdx.x;            // 0..31
    const int b = bh >> 3, h = bh & 7;
    const int n0 = blockIdx.y * 64;
    const int tid = threadIdx.x;

    // read 64 tokens x 64 dims
    {
        const int r = tid >> 1, cb = (tid & 1) * 32;
        const float* src = g_qkv + (size_t)(b * NN + n0 + r) * 1536 + 1024 + h * 64 + cb;
        #pragma unroll
        for (int c = 0; c < 8; c++) {
            float4 v = *(const float4*)&src[c * 4];
            float* d = &ts[r * 65 + cb + c * 4];
            d[0] = v.x; d[1] = v.y; d[2] = v.z; d[3] = v.w;
        }
    }
    __syncthreads();

    // write transposed: warp covers one dim row (32 words = 64 tokens)
    const int wp = tid >> 5, p = tid & 31;
    #pragma unroll
    for (int it = 0; it < 16; it++) {
        const int d = wp + it * 4;
        uint32_t word = pack_bf16(ts[(2 * p) * 65 + d], ts[(2 * p + 1) * 65 + d]);
        g_vtb[(size_t)(bh * 64 + d) * 1024 + (n0 >> 1) + p] = word;
    }
}

// ---------------------------- bf16 flash attention, cp.async 3-stage ring --
// 128 q per CTA, 8 warps x 16 q-rows, 64-key tiles. Q frags in regs,
// register-resident P, K/V tiles streamed with cp.async (no conversion).
#define VSW 36
#define STG_W (64 * VSW * 2)           // K + V per stage, words
#define VOFF_B (64 * VSW * 4)          // V offset within stage, bytes
#define ATT_SMEM (3 * STG_W * 4)       // 55296 B

__global__ __launch_bounds__(256, 2) void attn_bf16()
{
    extern __shared__ uint32_t sm[];
    const uint32_t sbase = (uint32_t)__cvta_generic_to_shared(sm);

    const int bh = blockIdx.y;
    const int q0 = blockIdx.x * 128;
    const uint32_t* __restrict__ Qw = g_qb + (size_t)bh * NN * 32;
    const uint32_t* __restrict__ Kw = g_kb + (size_t)bh * NN * 32;
    const uint32_t* __restrict__ Vw = g_vtb + (size_t)bh * 64 * 1024;

    const int tid  = threadIdx.x;
    const int w    = tid >> 5;
    const int lane = tid & 31;
    const int g    = lane >> 2;
    const int tg   = lane & 3;
    const int w16  = w * 16;

    // ---- Q fragments (bf16x2 words straight from gmem) ----
    uint32_t qa[4][4];
    {
        const int r0 = q0 + w16 + g, r1 = r0 + 8;
        #pragma unroll
        for (int ks = 0; ks < 4; ks++) {
            qa[ks][0] = Qw[r0 * 32 + ks * 8 + tg];
            qa[ks][1] = Qw[r1 * 32 + ks * 8 + tg];
            qa[ks][2] = Qw[r0 * 32 + ks * 8 + tg + 4];
            qa[ks][3] = Qw[r1 * 32 + ks * 8 + tg + 4];
        }
    }

    // per-thread cp.async coords: rows row0 and row0+32, 16B chunk cc
    const int row0 = tid >> 3;
    const int cc   = (tid & 7) * 4;                 // word offset in row
    const uint32_t dst0 = (uint32_t)(row0 * VSW + cc) * 4;
    const uint32_t dst1 = (uint32_t)((row0 + 32) * VSW + cc) * 4;

    float m0 = -1e30f, m1 = -1e30f, l0 = 0.f, l1 = 0.f;
    float oacc[8][4];
    #pragma unroll
    for (int nt = 0; nt < 8; nt++)
        #pragma unroll
        for (int q = 0; q < 4; q++) oacc[nt][q] = 0.f;

    // prologue: tiles 0,1 in flight
    #pragma unroll
    for (int s = 0; s < 2; s++) {
        const uint32_t sb = sbase + s * STG_W * 4;
        const int k0 = s * 64;
        cp_async16(sb + dst0, Kw + (k0 + row0) * 32 + cc);
        cp_async16(sb + dst1, Kw + (k0 + row0 + 32) * 32 + cc);
        cp_async16(sb + VOFF_B + dst0, Vw + row0 * 1024 + (k0 >> 1) + cc);
        cp_async16(sb + VOFF_B + dst1, Vw + (row0 + 32) * 1024 + (k0 >> 1) + cc);
        CP_COMMIT();
    }

    int stage = 0;
    for (int kt = 0; kt < 32; kt++) {
        CP_WAIT1();          // committed = kt+2 -> tiles <= kt done
        __syncthreads();     // arrivals visible; prev compute done (stage free)
        if (kt + 2 < 32) {
            const int s2 = (stage + 2 >= 3) ? stage - 1 : stage + 2;
            const uint32_t sb = sbase + s2 * STG_W * 4;
            const int k0 = (kt + 2) * 64;
            cp_async16(sb + dst0, Kw + (k0 + row0) * 32 + cc);
            cp_async16(sb + dst1, Kw + (k0 + row0 + 32) * 32 + cc);
            cp_async16(sb + VOFF_B + dst0, Vw + row0 * 1024 + (k0 >> 1) + cc);
            cp_async16(sb + VOFF_B + dst1, Vw + (row0 + 32) * 1024 + (k0 >> 1) + cc);
        }
        CP_COMMIT();         // always commit: keeps group invariant

        const uint32_t* Ks  = sm + stage * STG_W;
        const uint32_t* Vst = Ks + 64 * VSW;
        stage = (stage + 1 == 3) ? 0 : stage + 1;

        // ---- S = Q K^T ----
        float sacc[8][4];
        #pragma unroll
        for (int nt = 0; nt < 8; nt++)
            #pragma unroll
            for (int q = 0; q < 4; q++) sacc[nt][q] = 0.f;

        #pragma unroll
        for (int ks = 0; ks < 4; ks++) {
            const int wb = ks * 8;
            #pragma unroll
            for (int nt = 0; nt < 8; nt++) {
                const uint32_t* row = &Ks[(nt * 8 + g) * VSW];
                mma_bf16(sacc[nt], qa[ks], row[wb + tg], row[wb + 4 + tg]);
            }
        }

        // ---- online softmax (rows g / g+8) ----
        float mt0 = -1e30f, mt1 = -1e30f;
        #pragma unroll
        for (int nt = 0; nt < 8; nt++) {
            mt0 = fmaxf(mt0, fmaxf(sacc[nt][0], sacc[nt][1]));
            mt1 = fmaxf(mt1, fmaxf(sacc[nt][2], sacc[nt][3]));
        }
        mt0 = fmaxf(mt0, __shfl_xor_sync(0xffffffffu, mt0, 1));
        mt0 = fmaxf(mt0, __shfl_xor_sync(0xffffffffu, mt0, 2));
        mt1 = fmaxf(mt1, __shfl_xor_sync(0xffffffffu, mt1, 1));
        mt1 = fmaxf(mt1, __shfl_xor_sync(0xffffffffu, mt1, 2));
        float mn0 = fmaxf(m0, mt0), mn1 = fmaxf(m1, mt1);

        float rs0 = 0.f, rs1 = 0.f;
        #pragma unroll
        for (int nt = 0; nt < 8; nt++) {
            sacc[nt][0] = __expf(sacc[nt][0] - mn0);
            sacc[nt][1] = __expf(sacc[nt][1] - mn0);
            sacc[nt][2] = __expf(sacc[nt][2] - mn1);
            sacc[nt][3] = __expf(sacc[nt][3] - mn1);
            rs0 += sacc[nt][0] + sacc[nt][1];
            rs1 += sacc[nt][2] + sacc[nt][3];
        }
        rs0 += __shfl_xor_sync(0xffffffffu, rs0, 1);
        rs0 += __shfl_xor_sync(0xffffffffu, rs0, 2);
        rs1 += __shfl_xor_sync(0xffffffffu, rs1, 1);
        rs1 += __shfl_xor_sync(0xffffffffu, rs1, 2);

        float c0 = __expf(m0 - mn0), c1 = __expf(m1 - mn1);
        l0 = l0 * c0 + rs0;  l1 = l1 * c1 + rs1;
        m0 = mn0;            m1 = mn1;
        #pragma unroll
        for (int nt = 0; nt < 8; nt++) {
            oacc[nt][0] *= c0; oacc[nt][1] *= c0;
            oacc[nt][2] *= c1; oacc[nt][3] *= c1;
        }

        // ---- P to bf16 A-frags (registers only) ----
        uint32_t pa[8][2];
        #pragma unroll
        for (int nt = 0; nt < 8; nt++) {
            pa[nt][0] = pack_bf16(sacc[nt][0], sacc[nt][1]);
            pa[nt][1] = pack_bf16(sacc[nt][2], sacc[nt][3]);
        }

        // ---- O += P @ V ----
        #pragma unroll
        for (int ks = 0; ks < 4; ks++) {
            const int wb = ks * 8;
            uint32_t a[4] = { pa[2*ks][0], pa[2*ks][1],
                              pa[2*ks+1][0], pa[2*ks+1][1] };
            #pragma unroll
            for (int nt = 0; nt < 8; nt++) {
                const uint32_t* row = &Vst[(nt * 8 + g) * VSW];
                mma_bf16(oacc[nt], a, row[wb + tg], row[wb + 4 + tg]);
            }
        }
    }

    const int b = bh >> 3, h = bh & 7;
    const float inv0 = 1.f / l0, inv1 = 1.f / l1;
    const int r0 = q0 + w16 + g, r1 = r0 + 8;
    #pragma unroll
    for (int nt = 0; nt < 8; nt++) {
        int d = h * 64 + nt * 8 + tg * 2;
        *(float2*)&g_attn[(size_t)(b * NN + r0) * DD + d] =
            make_float2(roundtf(oacc[nt][0] * inv0), roundtf(oacc[nt][1] * inv0));
        *(float2*)&g_attn[(size_t)(b * NN + r1) * DD + d] =
            make_float2(roundtf(oacc[nt][2] * inv1), roundtf(oacc[nt][3] * inv1));
    }
}

// ------------------------------------------------------- LayerNorm + GELU --
__global__ __launch_bounds__(256) void ln_gelu_kernel(
    const float* __restrict__ gamma, const float* __restrict__ beta)
{
    const int r = blockIdx.x;
    const int t = threadIdx.x;
    float4 v = *(const float4*)&g_h1[(size_t)r * 1024 + t * 4];

    float sum = v.x + v.y + v.z + v.w;
    float sq  = v.x*v.x + v.y*v.y + v.z*v.z + v.w*v.w;
    #pragma unroll
    for (int off = 16; off >= 1; off >>= 1) {
        sum += __shfl_xor_sync(0xffffffffu, sum, off);
        sq  += __shfl_xor_sync(0xffffffffu, sq, off);
    }
    __shared__ float ssum[8], ssq[8];
    if ((t & 31) == 0) { ssum[t >> 5] = sum; ssq[t >> 5] = sq; }
    __syncthreads();
    float tot = 0.f, totq = 0.f;
    #pragma unroll
    for (int w = 0; w < 8; w++) { tot += ssum[w]; totq += ssq[w]; }

    float mean = tot * (1.f / 1024.f);
    float var  = totq * (1.f / 1024.f) - mean * mean;
    float inv  = rsqrtf(var + 1e-5f);

    float4 g4 = *(const float4*)&gamma[t * 4];
    float4 b4 = *(const float4*)&beta[t * 4];
    float y; float4 o;
    y = (v.x - mean) * inv * g4.x + b4.x; o.x = roundtf(0.5f * y * (1.f + erff(y * 0.70710678f)));
    y = (v.y - mean) * inv * g4.y + b4.y; o.y = roundtf(0.5f * y * (1.f + erff(y * 0.70710678f)));
    y = (v.z - mean) * inv * g4.z + b4.z; o.z = roundtf(0.5f * y * (1.f + erff(y * 0.70710678f)));
    y = (v.w - mean) * inv * g4.w + b4.w; o.w = roundtf(0.5f * y * (1.f + erff(y * 0.70710678f)));
    *(float4*)&g_h1[(size_t)r * 1024 + t * 4] = o;
}

// ------------------------------------------------------------- launcher ----
extern "C" void kernel_launch(void* const* d_in, const int* in_sizes, int n_in,
                              void* d_out, int out_size)
{
    const float* x      = (const float*)d_in[0];
    const float* freqs  = (const float*)d_in[1];
    const float* wqkv_w = (const float*)d_in[2];
    const float* wqkv_b = (const float*)d_in[3];
    const float* out_w  = (const float*)d_in[4];
    const float* out_b  = (const float*)d_in[5];
    const float* ffn1_w = (const float*)d_in[6];
    const float* ffn1_b = (const float*)d_in[7];
    const float* ln_g   = (const float*)d_in[8];
    const float* ln_b   = (const float*)d_in[9];
    const float* ffn2_w = (const float*)d_in[10];
    const float* ffn2_b = (const float*)d_in[11];
    float* out = (float*)d_out;

    float *p_qkv, *p_attn, *p_hcat, *p_h1, *p_xr, *p_wr;
    cudaGetSymbolAddress((void**)&p_qkv,  g_qkv);
    cudaGetSymbolAddress((void**)&p_attn, g_attn);
    cudaGetSymbolAddress((void**)&p_hcat, g_hcat);
    cudaGetSymbolAddress((void**)&p_h1,   g_h1);
    cudaGetSymbolAddress((void**)&p_xr,   g_xr);
    cudaGetSymbolAddress((void**)&p_wr,   g_wr);

    cudaFuncSetAttribute(gemm_tf32,
                         cudaFuncAttributeMaxDynamicSharedMemorySize, GEMM_SMEM);
    cudaFuncSetAttribute(attn_bf16,
                         cudaFuncAttributeMaxDynamicSharedMemorySize, ATT_SMEM);

    // 0. round x + all weights to tf32; also fill hcat[:,0:512]
    {
        int total_f4 = MROWS*DD/4 + (786432 + 262144 + 1048576 + 524288)/4;
        round_inputs<<<(total_f4 + 255)/256, 256>>>(x, wqkv_w, out_w, ffn1_w, ffn2_w);
    }

    // 1. QKV projection: [8192,512] @ [512,1536]
    gemm_tf32<<<dim3(1536/GBN, MROWS/GBM), 256, GEMM_SMEM>>>(
        p_xr, DD, p_wr + WOFF_QKV, 1536, p_qkv, 1536, wqkv_b, nullptr, 0, DD, 0);

    // 2. RoPE -> bf16 Q/K; V transpose -> bf16
    rope_kernel<<<(BB*NN*HH*32 + 255)/256, 256>>>(freqs);
    vtrans_kernel<<<dim3(BB*HH, NN/64), 128>>>();

    // 3. Attention (bf16 mma, cp.async 3-stage ring)
    attn_bf16<<<dim3(NN/128, BB*HH), 256, ATT_SMEM>>>();

    // 4. out-proj into hcat right half (rounded): [8192,512]@[512,512]
    gemm_tf32<<<dim3(512/GBN, MROWS/GBM), 256, GEMM_SMEM>>>(
        p_attn, DD, p_wr + WOFF_OUT, DD, p_hcat + 512, 1024, out_b, nullptr, 0, DD, 1);

    // 5. FFN1: [8192,1024]@[1024,1024]
    gemm_tf32<<<dim3(1024/GBN, MROWS/GBM), 256, GEMM_SMEM>>>(
        p_hcat, 1024, p_wr + WOFF_FFN1, 1024, p_h1, 1024, ffn1_b, nullptr, 0, 1024, 0);

    // 6. LayerNorm + exact GELU (in place, stores rounded)
    ln_gelu_kernel<<<MROWS, 256>>>(ln_g, ln_b);

    // 7. FFN2 + residual: out = x + h1 @ [1024,512] + b
    gemm_tf32<<<dim3(512/GBN, MROWS/GBM), 256, GEMM_SMEM>>>(
        p_h1, 1024, p_wr + WOFF_FFN2, DD, out, DD, ffn2_b, x, DD, 1024, 0);
}

// round 10
// speedup vs baseline: 1.6227x; 1.0541x over previous
#include <cuda_runtime.h>
#include <cuda_bf16.h>
#include <math.h>
#include <stdint.h>

// Problem constants
#define BB 4
#define NN 2048
#define DD 512
#define HH 8
#define HDIM 64
#define MROWS (BB*NN)          // 8192

// ---------------- scratch (static device globals; no runtime allocation) ---
__device__ float g_qkv[MROWS*1536];
__device__ float g_attn[MROWS*DD];
__device__ float g_hcat[MROWS*1024];
__device__ float g_h1[MROWS*1024];
__device__ float g_xr[MROWS*DD];          // tf32-rounded x
__device__ float g_wr[2621440];           // tf32-rounded weights, [N][K], pi-permuted K
__device__ uint32_t g_qb[MROWS*256];      // bf16x2 Q [bh][n][d/2], pre-scaled
__device__ uint32_t g_kb[MROWS*256];      // bf16x2 K [bh][n][d/2]
__device__ uint32_t g_vtb[MROWS*256];     // bf16x2 V^T [bh][d][n/2]

#define WOFF_QKV  0                        // [1536][512]
#define WOFF_OUT  786432                   // [512][512]
#define WOFF_FFN1 1048576                  // [1024][1024]
#define WOFF_FFN2 2097152                  // [512][1024]

// ------------------------------------------------------------ tf32 utils ---
__device__ __forceinline__ uint32_t f2tf32(float x) {
    uint32_t u;
    asm volatile("cvt.rna.tf32.f32 %0, %1;" : "=r"(u) : "f"(x));
    return u;
}
__device__ __forceinline__ float roundtf(float x) {
    return __uint_as_float(f2tf32(x));
}
// pack two f32 -> bf16x2 (lo = a, hi = b)
__device__ __forceinline__ uint32_t pack_bf16(float a, float b) {
    uint32_t r;
    asm("cvt.rn.bf16x2.f32 %0, %1, %2;" : "=r"(r) : "f"(b), "f"(a));
    return r;
}

__device__ __forceinline__ void mma_tf32(float c[4],
                                         const uint32_t a[4],
                                         const uint32_t b[2]) {
    asm volatile(
        "mma.sync.aligned.m16n8k8.row.col.f32.tf32.tf32.f32 "
        "{%0,%1,%2,%3}, {%4,%5,%6,%7}, {%8,%9}, {%0,%1,%2,%3};\n"
        : "+f"(c[0]), "+f"(c[1]), "+f"(c[2]), "+f"(c[3])
        : "r"(a[0]), "r"(a[1]), "r"(a[2]), "r"(a[3]),
          "r"(b[0]), "r"(b[1]));
}

__device__ __forceinline__ void mma_bf16(float c[4],
                                         const uint32_t a[4],
                                         uint32_t b0, uint32_t b1) {
    asm volatile(
        "mma.sync.aligned.m16n8k16.row.col.f32.bf16.bf16.f32 "
        "{%0,%1,%2,%3}, {%4,%5,%6,%7}, {%8,%9}, {%0,%1,%2,%3};\n"
        : "+f"(c[0]), "+f"(c[1]), "+f"(c[2]), "+f"(c[3])
        : "r"(a[0]), "r"(a[1]), "r"(a[2]), "r"(a[3]),
          "r"(b0), "r"(b1));
}

__device__ __forceinline__ void cp_async16(uint32_t saddr, const void* gptr) {
    asm volatile("cp.async.cg.shared.global [%0], [%1], 16;\n"
                 :: "r"(saddr), "l"(gptr));
}
#define CP_COMMIT() asm volatile("cp.async.commit_group;\n" ::: "memory")
#define CP_WAIT1()  asm volatile("cp.async.wait_group 1;\n" ::: "memory")
#define CP_WAIT2()  asm volatile("cp.async.wait_group 2;\n" ::: "memory")

// --------------------------- pre-round x, fill hcat left half --------------
__global__ __launch_bounds__(256) void round_x(const float* __restrict__ x)
{
    int idx = blockIdx.x * blockDim.x + threadIdx.x;  // float4 index
    if (idx >= MROWS*DD/4) return;
    float4 v = ((const float4*)x)[idx];
    v.x = roundtf(v.x); v.y = roundtf(v.y);
    v.z = roundtf(v.z); v.w = roundtf(v.w);
    ((float4*)g_xr)[idx] = v;
    int m = idx >> 7, j = idx & 127;
    ((float4*)g_hcat)[m * 256 + j] = v;
}

// ------------------- transpose + round + pi-permute weights ----------------
// src [K][N] -> dst [N][K] with K words permuted within 8-groups:
// pi(k) = (k&~7) | ((k&3)<<1) | ((k>>2)&1).  grid (N/32, K/32), block (32,8).
__global__ __launch_bounds__(256) void transpose_round_pi(
    const float* __restrict__ src, float* __restrict__ dst, int K, int N)
{
    __shared__ float t[32][33];
    int k0 = blockIdx.y * 32, n0 = blockIdx.x * 32;
    int x = threadIdx.x, y = threadIdx.y;
    #pragma unroll
    for (int j = 0; j < 4; j++)
        t[y + 8*j][x] = src[(size_t)(k0 + y + 8*j) * N + n0 + x];
    __syncthreads();
    const int px = (x & ~7) | ((x & 3) << 1) | ((x >> 2) & 1);
    #pragma unroll
    for (int j = 0; j < 4; j++)
        dst[(size_t)(n0 + y + 8*j) * K + k0 + px] = roundtf(t[x][y + 8*j]);
}

// ---------------- 4-stage pipelined tf32 GEMM, 64x64 warp tiles ------------
// A [M][K] natural layout, pad 20.  Bt [N][K] pi-permuted K, pad 24
// -> B-fragment pairs adjacent (LDS.64), banks conflict-free.
#define GBM 128
#define GBN 128
#define GBK 16
#define APADW 20
#define BPADW 24
#define BOFF_W (GBM*APADW)                    // 2560 words
#define STAGE_W (GBM*APADW + GBN*BPADW)       // 5632 words
#define STAGE_B (STAGE_W*4)                   // 22528 bytes
#define GEMM_SMEM (4*STAGE_B)                 // 90112 bytes

__global__ __launch_bounds__(128) void gemm_tf32(
    const float* __restrict__ A, int lda,
    const float* __restrict__ Bt, int ldb,
    float* __restrict__ C, int ldc,
    const float* __restrict__ bias,
    const float* __restrict__ res, int ldres,
    int K, int roundC)
{
    extern __shared__ uint32_t gsm[];
    const uint32_t sbase = (uint32_t)__cvta_generic_to_shared(gsm);

    const int tid  = threadIdx.x;
    const int brow = blockIdx.y * GBM;
    const int bcol = blockIdx.x * GBN;
    const int w    = tid >> 5;
    const int lane = tid & 31;
    const int g    = lane >> 2;
    const int tg   = lane & 3;
    const int wm   = (w & 1) * 64;
    const int wn   = (w >> 1) * 64;

    // per-thread load coords: 512 chunks (16B) per tile, 4 per thread per tile
    int arow[4], achk[4];
    uint32_t offA[4], offB[4];
    #pragma unroll
    for (int i = 0; i < 4; i++) {
        int idx = tid + i * 128;         // 0..511
        arow[i] = idx >> 2;
        achk[i] = (idx & 3) * 4;
        offA[i] = (uint32_t)(arow[i] * APADW + achk[i]) * 4;
        offB[i] = (uint32_t)(BOFF_W + arow[i] * BPADW + achk[i]) * 4;
    }

    float acc[4][8][4];
    #pragma unroll
    for (int mi = 0; mi < 4; mi++)
        #pragma unroll
        for (int ni = 0; ni < 8; ni++)
            #pragma unroll
            for (int q = 0; q < 4; q++) acc[mi][ni][q] = 0.f;

    const int nk = K / GBK;

    // prologue: stages 0,1,2 in flight
    #pragma unroll
    for (int s = 0; s < 3; s++) {
        const uint32_t sb = sbase + s * STAGE_B;
        const int k0 = s * GBK;
        #pragma unroll
        for (int i = 0; i < 4; i++) {
            cp_async16(sb + offA[i], &A[(size_t)(brow + arow[i]) * lda + k0 + achk[i]]);
            cp_async16(sb + offB[i], &Bt[(size_t)(bcol + arow[i]) * ldb + k0 + achk[i]]);
        }
        CP_COMMIT();
    }

    for (int kt = 0; kt < nk; kt++) {
        CP_WAIT2();
        __syncthreads();
        if (kt + 3 < nk) {
            const uint32_t sb = sbase + ((kt + 3) & 3) * STAGE_B;
            const int k0 = (kt + 3) * GBK;
            #pragma unroll
            for (int i = 0; i < 4; i++) {
                cp_async16(sb + offA[i], &A[(size_t)(brow + arow[i]) * lda + k0 + achk[i]]);
                cp_async16(sb + offB[i], &Bt[(size_t)(bcol + arow[i]) * ldb + k0 + achk[i]]);
            }
        }
        CP_COMMIT();   // always commit: keeps group-count invariant

        const uint32_t* Asb = gsm + (kt & 3) * STAGE_W;
        const uint32_t* Bsb = Asb + BOFF_W;

        #pragma unroll
        for (int ks = 0; ks < 2; ks++) {
            const int kk = ks * 8;
            uint32_t af[4][4], bf[8][2];
            #pragma unroll
            for (int mi = 0; mi < 4; mi++) {
                int r = wm + mi * 16 + g;
                af[mi][0] = Asb[r * APADW + kk + tg];
                af[mi][1] = Asb[(r + 8) * APADW + kk + tg];
                af[mi][2] = Asb[r * APADW + kk + tg + 4];
                af[mi][3] = Asb[(r + 8) * APADW + kk + tg + 4];
            }
            #pragma unroll
            for (int ni = 0; ni < 8; ni++) {
                int c = wn + ni * 8 + g;
                uint2 bv = *(const uint2*)&Bsb[c * BPADW + kk + 2 * tg];
                bf[ni][0] = bv.x; bf[ni][1] = bv.y;
            }
            #pragma unroll
            for (int mi = 0; mi < 4; mi++)
                #pragma unroll
                for (int ni = 0; ni < 8; ni++)
                    mma_tf32(acc[mi][ni], af[mi], bf[ni]);
        }
    }

    #pragma unroll
    for (int mi = 0; mi < 4; mi++) {
        int r0 = brow + wm + mi * 16 + g;
        int r1 = r0 + 8;
        #pragma unroll
        for (int ni = 0; ni < 8; ni++) {
            int cc = bcol + wn + ni * 8 + tg * 2;
            float2 b2 = *(const float2*)&bias[cc];
            float v0 = acc[mi][ni][0] + b2.x;
            float v1 = acc[mi][ni][1] + b2.y;
            float v2 = acc[mi][ni][2] + b2.x;
            float v3 = acc[mi][ni][3] + b2.y;
            if (res) {
                float2 ra = *(const float2*)&res[(size_t)r0 * ldres + cc];
                float2 rb = *(const float2*)&res[(size_t)r1 * ldres + cc];
                v0 += ra.x; v1 += ra.y; v2 += rb.x; v3 += rb.y;
            }
            if (roundC) {
                v0 = roundtf(v0); v1 = roundtf(v1);
                v2 = roundtf(v2); v3 = roundtf(v3);
            }
            *(float2*)&C[(size_t)r0 * ldc + cc] = make_float2(v0, v1);
            *(float2*)&C[(size_t)r1 * ldc + cc] = make_float2(v2, v3);
        }
    }
}

// ------------------------------------------------------------ RoPE split ---
__global__ void rope_kernel(const float* __restrict__ freqs)
{
    int idx = blockIdx.x * blockDim.x + threadIdx.x;
    if (idx >= BB * NN * HH * 32) return;
    int i = idx & 31;
    int h = (idx >> 5) & 7;
    int n = (idx >> 8) & 2047;
    int b = idx >> 19;

    float f = freqs[(b * NN + n) * 32 + i];
    float c = cosf(f), s = sinf(f);

    int base = (b * NN + n) * 1536 + h * 64;
    int ow   = ((b * HH + h) * NN + n) * 32 + i;

    float q1 = g_qkv[base + 2*i], q2 = g_qkv[base + 2*i + 1];
    g_qb[ow] = pack_bf16((q1 * c - q2 * s) * 0.125f,
                         (q1 * s + q2 * c) * 0.125f);

    float k1 = g_qkv[base + 512 + 2*i], k2 = g_qkv[base + 512 + 2*i + 1];
    g_kb[ow] = pack_bf16(k1 * c - k2 * s, k1 * s + k2 * c);
}

// ----------------------------------------------- V transpose to bf16x2 -----
__global__ __launch_bounds__(128) void vtrans_kernel()
{
    __shared__ float ts[64 * 65];
    const int bh = blockIdx.x;
    const int b = bh >> 3, h = bh & 7;
    const int n0 = blockIdx.y * 64;
    const int tid = threadIdx.x;

    {
        const int r = tid >> 1, cb = (tid & 1) * 32;
        const float* src = g_qkv + (size_t)(b * NN + n0 + r) * 1536 + 1024 + h * 64 + cb;
        #pragma unroll
        for (int c = 0; c < 8; c++) {
            float4 v = *(const float4*)&src[c * 4];
            float* d = &ts[r * 65 + cb + c * 4];
            d[0] = v.x; d[1] = v.y; d[2] = v.z; d[3] = v.w;
        }
    }
    __syncthreads();

    const int wp = tid >> 5, p = tid & 31;
    #pragma unroll
    for (int it = 0; it < 16; it++) {
        const int d = wp + it * 4;
        uint32_t word = pack_bf16(ts[(2 * p) * 65 + d], ts[(2 * p + 1) * 65 + d]);
        g_vtb[(size_t)(bh * 64 + d) * 1024 + (n0 >> 1) + p] = word;
    }
}

// ---------------------------- bf16 flash attention, cp.async 3-stage ring --
#define VSW 36
#define STG_W (64 * VSW * 2)
#define VOFF_B (64 * VSW * 4)
#define ATT_SMEM (3 * STG_W * 4)       // 55296 B

__global__ __launch_bounds__(256, 2) void attn_bf16()
{
    extern __shared__ uint32_t sm[];
    const uint32_t sbase = (uint32_t)__cvta_generic_to_shared(sm);

    const int bh = blockIdx.y;
    const int q0 = blockIdx.x * 128;
    const uint32_t* __restrict__ Qw = g_qb + (size_t)bh * NN * 32;
    const uint32_t* __restrict__ Kw = g_kb + (size_t)bh * NN * 32;
    const uint32_t* __restrict__ Vw = g_vtb + (size_t)bh * 64 * 1024;

    const int tid  = threadIdx.x;
    const int w    = tid >> 5;
    const int lane = tid & 31;
    const int g    = lane >> 2;
    const int tg   = lane & 3;
    const int w16  = w * 16;

    uint32_t qa[4][4];
    {
        const int r0 = q0 + w16 + g, r1 = r0 + 8;
        #pragma unroll
        for (int ks = 0; ks < 4; ks++) {
            qa[ks][0] = Qw[r0 * 32 + ks * 8 + tg];
            qa[ks][1] = Qw[r1 * 32 + ks * 8 + tg];
            qa[ks][2] = Qw[r0 * 32 + ks * 8 + tg + 4];
            qa[ks][3] = Qw[r1 * 32 + ks * 8 + tg + 4];
        }
    }

    const int row0 = tid >> 3;
    const int cc   = (tid & 7) * 4;
    const uint32_t dst0 = (uint32_t)(row0 * VSW + cc) * 4;
    const uint32_t dst1 = (uint32_t)((row0 + 32) * VSW + cc) * 4;

    float m0 = -1e30f, m1 = -1e30f, l0 = 0.f, l1 = 0.f;
    float oacc[8][4];
    #pragma unroll
    for (int nt = 0; nt < 8; nt++)
        #pragma unroll
        for (int q = 0; q < 4; q++) oacc[nt][q] = 0.f;

    #pragma unroll
    for (int s = 0; s < 2; s++) {
        const uint32_t sb = sbase + s * STG_W * 4;
        const int k0 = s * 64;
        cp_async16(sb + dst0, Kw + (k0 + row0) * 32 + cc);
        cp_async16(sb + dst1, Kw + (k0 + row0 + 32) * 32 + cc);
        cp_async16(sb + VOFF_B + dst0, Vw + row0 * 1024 + (k0 >> 1) + cc);
        cp_async16(sb + VOFF_B + dst1, Vw + (row0 + 32) * 1024 + (k0 >> 1) + cc);
        CP_COMMIT();
    }

    int stage = 0;
    for (int kt = 0; kt < 32; kt++) {
        CP_WAIT1();
        __syncthreads();
        if (kt + 2 < 32) {
            const int s2 = (stage + 2 >= 3) ? stage - 1 : stage + 2;
            const uint32_t sb = sbase + s2 * STG_W * 4;
            const int k0 = (kt + 2) * 64;
            cp_async16(sb + dst0, Kw + (k0 + row0) * 32 + cc);
            cp_async16(sb + dst1, Kw + (k0 + row0 + 32) * 32 + cc);
            cp_async16(sb + VOFF_B + dst0, Vw + row0 * 1024 + (k0 >> 1) + cc);
            cp_async16(sb + VOFF_B + dst1, Vw + (row0 + 32) * 1024 + (k0 >> 1) + cc);
        }
        CP_COMMIT();

        const uint32_t* Ks  = sm + stage * STG_W;
        const uint32_t* Vst = Ks + 64 * VSW;
        stage = (stage + 1 == 3) ? 0 : stage + 1;

        float sacc[8][4];
        #pragma unroll
        for (int nt = 0; nt < 8; nt++)
            #pragma unroll
            for (int q = 0; q < 4; q++) sacc[nt][q] = 0.f;

        #pragma unroll
        for (int ks = 0; ks < 4; ks++) {
            const int wb = ks * 8;
            #pragma unroll
            for (int nt = 0; nt < 8; nt++) {
                const uint32_t* row = &Ks[(nt * 8 + g) * VSW];
                mma_bf16(sacc[nt], qa[ks], row[wb + tg], row[wb + 4 + tg]);
            }
        }

        float mt0 = -1e30f, mt1 = -1e30f;
        #pragma unroll
        for (int nt = 0; nt < 8; nt++) {
            mt0 = fmaxf(mt0, fmaxf(sacc[nt][0], sacc[nt][1]));
            mt1 = fmaxf(mt1, fmaxf(sacc[nt][2], sacc[nt][3]));
        }
        mt0 = fmaxf(mt0, __shfl_xor_sync(0xffffffffu, mt0, 1));
        mt0 = fmaxf(mt0, __shfl_xor_sync(0xffffffffu, mt0, 2));
        mt1 = fmaxf(mt1, __shfl_xor_sync(0xffffffffu, mt1, 1));
        mt1 = fmaxf(mt1, __shfl_xor_sync(0xffffffffu, mt1, 2));
        float mn0 = fmaxf(m0, mt0), mn1 = fmaxf(m1, mt1);

        float rs0 = 0.f, rs1 = 0.f;
        #pragma unroll
        for (int nt = 0; nt < 8; nt++) {
            sacc[nt][0] = __expf(sacc[nt][0] - mn0);
            sacc[nt][1] = __expf(sacc[nt][1] - mn0);
            sacc[nt][2] = __expf(sacc[nt][2] - mn1);
            sacc[nt][3] = __expf(sacc[nt][3] - mn1);
            rs0 += sacc[nt][0] + sacc[nt][1];
            rs1 += sacc[nt][2] + sacc[nt][3];
        }
        rs0 += __shfl_xor_sync(0xffffffffu, rs0, 1);
        rs0 += __shfl_xor_sync(0xffffffffu, rs0, 2);
        rs1 += __shfl_xor_sync(0xffffffffu, rs1, 1);
        rs1 += __shfl_xor_sync(0xffffffffu, rs1, 2);

        float c0 = __expf(m0 - mn0), c1 = __expf(m1 - mn1);
        l0 = l0 * c0 + rs0;  l1 = l1 * c1 + rs1;
        m0 = mn0;            m1 = mn1;
        #pragma unroll
        for (int nt = 0; nt < 8; nt++) {
            oacc[nt][0] *= c0; oacc[nt][1] *= c0;
            oacc[nt][2] *= c1; oacc[nt][3] *= c1;
        }

        uint32_t pa[8][2];
        #pragma unroll
        for (int nt = 0; nt < 8; nt++) {
            pa[nt][0] = pack_bf16(sacc[nt][0], sacc[nt][1]);
            pa[nt][1] = pack_bf16(sacc[nt][2], sacc[nt][3]);
        }

        #pragma unroll
        for (int ks = 0; ks < 4; ks++) {
            const int wb = ks * 8;
            uint32_t a[4] = { pa[2*ks][0], pa[2*ks][1],
                              pa[2*ks+1][0], pa[2*ks+1][1] };
            #pragma unroll
            for (int nt = 0; nt < 8; nt++) {
                const uint32_t* row = &Vst[(nt * 8 + g) * VSW];
                mma_bf16(oacc[nt], a, row[wb + tg], row[wb + 4 + tg]);
            }
        }
    }

    const int b = bh >> 3, h = bh & 7;
    const float inv0 = 1.f / l0, inv1 = 1.f / l1;
    const int r0 = q0 + w16 + g, r1 = r0 + 8;
    #pragma unroll
    for (int nt = 0; nt < 8; nt++) {
        int d = h * 64 + nt * 8 + tg * 2;
        *(float2*)&g_attn[(size_t)(b * NN + r0) * DD + d] =
            make_float2(roundtf(oacc[nt][0] * inv0), roundtf(oacc[nt][1] * inv0));
        *(float2*)&g_attn[(size_t)(b * NN + r1) * DD + d] =
            make_float2(roundtf(oacc[nt][2] * inv1), roundtf(oacc[nt][3] * inv1));
    }
}

// ------------------------------------------------------- LayerNorm + GELU --
__global__ __launch_bounds__(256) void ln_gelu_kernel(
    const float* __restrict__ gamma, const float* __restrict__ beta)
{
    const int r = blockIdx.x;
    const int t = threadIdx.x;
    float4 v = *(const float4*)&g_h1[(size_t)r * 1024 + t * 4];

    float sum = v.x + v.y + v.z + v.w;
    float sq  = v.x*v.x + v.y*v.y + v.z*v.z + v.w*v.w;
    #pragma unroll
    for (int off = 16; off >= 1; off >>= 1) {
        sum += __shfl_xor_sync(0xffffffffu, sum, off);
        sq  += __shfl_xor_sync(0xffffffffu, sq, off);
    }
    __shared__ float ssum[8], ssq[8];
    if ((t & 31) == 0) { ssum[t >> 5] = sum; ssq[t >> 5] = sq; }
    __syncthreads();
    float tot = 0.f, totq = 0.f;
    #pragma unroll
    for (int w = 0; w < 8; w++) { tot += ssum[w]; totq += ssq[w]; }

    float mean = tot * (1.f / 1024.f);
    float var  = totq * (1.f / 1024.f) - mean * mean;
    float inv  = rsqrtf(var + 1e-5f);

    float4 g4 = *(const float4*)&gamma[t * 4];
    float4 b4 = *(const float4*)&beta[t * 4];
    float y; float4 o;
    y = (v.x - mean) * inv * g4.x + b4.x; o.x = roundtf(0.5f * y * (1.f + erff(y * 0.70710678f)));
    y = (v.y - mean) * inv * g4.y + b4.y; o.y = roundtf(0.5f * y * (1.f + erff(y * 0.70710678f)));
    y = (v.z - mean) * inv * g4.z + b4.z; o.z = roundtf(0.5f * y * (1.f + erff(y * 0.70710678f)));
    y = (v.w - mean) * inv * g4.w + b4.w; o.w = roundtf(0.5f * y * (1.f + erff(y * 0.70710678f)));
    *(float4*)&g_h1[(size_t)r * 1024 + t * 4] = o;
}

// ------------------------------------------------------------- launcher ----
extern "C" void kernel_launch(void* const* d_in, const int* in_sizes, int n_in,
                              void* d_out, int out_size)
{
    const float* x      = (const float*)d_in[0];
    const float* freqs  = (const float*)d_in[1];
    const float* wqkv_w = (const float*)d_in[2];
    const float* wqkv_b = (const float*)d_in[3];
    const float* out_w  = (const float*)d_in[4];
    const float* out_b  = (const float*)d_in[5];
    const float* ffn1_w = (const float*)d_in[6];
    const float* ffn1_b = (const float*)d_in[7];
    const float* ln_g   = (const float*)d_in[8];
    const float* ln_b   = (const float*)d_in[9];
    const float* ffn2_w = (const float*)d_in[10];
    const float* ffn2_b = (const float*)d_in[11];
    float* out = (float*)d_out;

    float *p_qkv, *p_attn, *p_hcat, *p_h1, *p_xr, *p_wr;
    cudaGetSymbolAddress((void**)&p_qkv,  g_qkv);
    cudaGetSymbolAddress((void**)&p_attn, g_attn);
    cudaGetSymbolAddress((void**)&p_hcat, g_hcat);
    cudaGetSymbolAddress((void**)&p_h1,   g_h1);
    cudaGetSymbolAddress((void**)&p_xr,   g_xr);
    cudaGetSymbolAddress((void**)&p_wr,   g_wr);

    cudaFuncSetAttribute(gemm_tf32,
                         cudaFuncAttributeMaxDynamicSharedMemorySize, GEMM_SMEM);
    cudaFuncSetAttribute(attn_bf16,
                         cudaFuncAttributeMaxDynamicSharedMemorySize, ATT_SMEM);

    // 0a. round x, fill hcat left half
    round_x<<<(MROWS*DD/4 + 255)/256, 256>>>(x);
    // 0b. transpose + round + pi-permute weights ([K][N] -> [N][K])
    transpose_round_pi<<<dim3(1536/32, 512/32),  dim3(32,8)>>>(wqkv_w, p_wr + WOFF_QKV, 512, 1536);
    transpose_round_pi<<<dim3(512/32,  512/32),  dim3(32,8)>>>(out_w,  p_wr + WOFF_OUT, 512, 512);
    transpose_round_pi<<<dim3(1024/32, 1024/32), dim3(32,8)>>>(ffn1_w, p_wr + WOFF_FFN1, 1024, 1024);
    transpose_round_pi<<<dim3(512/32,  1024/32), dim3(32,8)>>>(ffn2_w, p_wr + WOFF_FFN2, 1024, 512);

    // 1. QKV projection: [8192,512] @ [512,1536]
    gemm_tf32<<<dim3(1536/GBN, MROWS/GBM), 128, GEMM_SMEM>>>(
        p_xr, DD, p_wr + WOFF_QKV, 512, p_qkv, 1536, wqkv_b, nullptr, 0, DD, 0);

    // 2. RoPE -> bf16 Q/K; V transpose -> bf16
    rope_kernel<<<(BB*NN*HH*32 + 255)/256, 256>>>(freqs);
    vtrans_kernel<<<dim3(BB*HH, NN/64), 128>>>();

    // 3. Attention (bf16 mma, cp.async 3-stage ring)
    attn_bf16<<<dim3(NN/128, BB*HH), 256, ATT_SMEM>>>();

    // 4. out-proj into hcat right half (rounded): [8192,512]@[512,512]
    gemm_tf32<<<dim3(512/GBN, MROWS/GBM), 128, GEMM_SMEM>>>(
        p_attn, DD, p_wr + WOFF_OUT, 512, p_hcat + 512, 1024, out_b, nullptr, 0, DD, 1);

    // 5. FFN1: [8192,1024]@[1024,1024]
    gemm_tf32<<<dim3(1024/GBN, MROWS/GBM), 128, GEMM_SMEM>>>(
        p_hcat, 1024, p_wr + WOFF_FFN1, 1024, p_h1, 1024, ffn1_b, nullptr, 0, 1024, 0);

    // 6. LayerNorm + exact GELU (in place, stores rounded)
    ln_gelu_kernel<<<MROWS, 256>>>(ln_g, ln_b);

    // 7. FFN2 + residual: out = x + h1 @ [1024,512] + b
    gemm_tf32<<<dim3(512/GBN, MROWS/GBM), 128, GEMM_SMEM>>>(
        p_h1, 1024, p_wr + WOFF_FFN2, 1024, out, DD, ffn2_b, x, DD, 1024, 0);
}